// round 6
// baseline (speedup 1.0000x reference)
#include <cuda_runtime.h>
#include <cuda_bf16.h>
#include <math.h>

// ---------------- problem constants ----------------
#define T_TYPES 4
#define R_RELS 6
#define HID 64
#define HEADS 8
#define DH 8
#define LAYERS 2
#define OUT_DIM 4

static const int N_[T_TYPES]   = {100000, 200000, 20000, 2000};
static const int F_[T_TYPES]   = {334, 512, 128, 128};
static const int OFF_[T_TYPES] = {0, 100000, 300000, 320000};
#define NTOT 322000
static const int E_[R_RELS]  = {800000, 800000, 1000000, 1000000, 200000, 200000};
static const int RS_[R_RELS] = {0, 1, 1, 2, 1, 3};   // src type
static const int RD_[R_RELS] = {1, 0, 2, 1, 3, 1};   // dst type

// per-relation dst segmentation (cumulative)
static const int CUMND_[R_RELS + 1] = {0, 200000, 300000, 320000, 520000, 522000, 722000};
#define NDSUM 722000
// per-relation src segmentation (cumulative)
static const int CUMSRC_[R_RELS + 1] = {0, 100000, 300000, 500000, 520000, 720000, 722000};
#define SRCSUM 722000
#define ESUM  4000000

// attention: blocks per relation (32 dst nodes / block)
static const int ABLK_[R_RELS + 1] = {0, 6250, 9375, 10000, 16250, 16313, 22563};
#define ATTN_BLOCKS 22563

// ---------------- device scratch (static, no allocation) ----------------
__device__ float    g_h[NTOT * HID];
__device__ float    g_Q[NTOT * HID];
__device__ float    g_Kt[SRCSUM * HID];     // per-relation transformed K (P*scale folded)
__device__ float    g_Vt[SRCSUM * HID];     // per-relation transformed V
__device__ float    g_acc[NDSUM * HID];     // per-relation normalized attention output
__device__ unsigned g_cnt[NDSUM];
__device__ int      g_rowptr[NDSUM + 1];
__device__ int      g_cur[NDSUM];
__device__ int      g_bsum[512];
__device__ int      g_srcs[ESUM];

// ---------------- helpers ----------------
__device__ __forceinline__ float gelu_exact(float x) {
    return 0.5f * x * (1.0f + erff(x * 0.70710678118654752f));
}

__global__ void fill4_u32(uint4* p, unsigned v, int n4) {
    int i = blockIdx.x * blockDim.x + threadIdx.x;
    uint4 val = make_uint4(v, v, v, v);
    for (; i < n4; i += gridDim.x * blockDim.x) p[i] = val;
}

// ---------------- CSR build ----------------
__global__ void count_kernel(const int* __restrict__ dst, unsigned* __restrict__ cnt, int E) {
    int e = blockIdx.x * blockDim.x + threadIdx.x;
    if (e < E) atomicAdd(&cnt[dst[e]], 1u);
}

__global__ void scan1_kernel(const unsigned* __restrict__ cnt, int* __restrict__ row,
                             int* __restrict__ bsum, int n) {
    __shared__ int sm[256];
    int tid = threadIdx.x;
    int base = blockIdx.x * 2048 + tid * 8;
    int vals[8];
    int s = 0;
    #pragma unroll
    for (int i = 0; i < 8; i++) {
        int idx = base + i;
        int t = (idx < n) ? (int)cnt[idx] : 0;
        vals[i] = s;
        s += t;
    }
    sm[tid] = s;
    __syncthreads();
    #pragma unroll
    for (int off = 1; off < 256; off <<= 1) {
        int t = (tid >= off) ? sm[tid - off] : 0;
        __syncthreads();
        sm[tid] += t;
        __syncthreads();
    }
    int excl = sm[tid] - s;
    if (tid == 255) bsum[blockIdx.x] = sm[255];
    #pragma unroll
    for (int i = 0; i < 8; i++) {
        int idx = base + i;
        if (idx < n) row[idx] = excl + vals[i];
    }
}

__global__ void scan2_kernel(int* __restrict__ bsum, int nb) {
    __shared__ int sm[512];
    int tid = threadIdx.x;
    int v = (tid < nb) ? bsum[tid] : 0;
    sm[tid] = v;
    __syncthreads();
    #pragma unroll
    for (int off = 1; off < 512; off <<= 1) {
        int t = (tid >= off) ? sm[tid - off] : 0;
        __syncthreads();
        sm[tid] += t;
        __syncthreads();
    }
    if (tid < nb) bsum[tid] = sm[tid] - v;
}

__global__ void scan3_kernel(int* __restrict__ row, int* __restrict__ cur,
                             const int* __restrict__ bsum, int n, int total) {
    int idx = blockIdx.x * blockDim.x + threadIdx.x;
    if (idx < n) {
        int v = row[idx] + bsum[idx >> 11];
        row[idx] = v;
        cur[idx] = v;
    }
    if (idx == 0) row[n] = total;
}

__global__ void scatter_kernel(const int* __restrict__ src, const int* __restrict__ dst,
                               int* __restrict__ cur, int* __restrict__ srcs, int E) {
    int e = blockIdx.x * blockDim.x + threadIdx.x;
    if (e >= E) return;
    int pos = atomicAdd(&cur[dst[e]], 1);
    srcs[pos] = src[e];
}

// ---------------- input projection GEMM: Y = relu(X[M,K] @ W[K,64] + B) ----------------
__global__ void gemm_in_kernel(const float* __restrict__ X, const float* __restrict__ W,
                               const float* __restrict__ B, float* __restrict__ Y,
                               int M, int K) {
    __shared__ float xs[128][33];
    __shared__ float ws[32][64];
    int tid = threadIdx.x;
    int tx = tid & 15, ty = tid >> 4;
    int rowBase = blockIdx.x * 128;
    float acc[8][4] = {};
    for (int k0 = 0; k0 < K; k0 += 32) {
        #pragma unroll
        for (int it = 0; it < 16; it++) {
            int idx = tid + it * 256;
            int r = idx >> 5, c = idx & 31;
            int gr = rowBase + r, gc = k0 + c;
            xs[r][c] = (gr < M && gc < K) ? X[(size_t)gr * K + gc] : 0.0f;
        }
        #pragma unroll
        for (int it = 0; it < 8; it++) {
            int idx = tid + it * 256;
            int kk = idx >> 6, c = idx & 63;
            int gk = k0 + kk;
            ws[kk][c] = (gk < K) ? W[(size_t)gk * 64 + c] : 0.0f;
        }
        __syncthreads();
        #pragma unroll
        for (int kk = 0; kk < 32; kk++) {
            float a[8], b[4];
            #pragma unroll
            for (int i = 0; i < 8; i++) a[i] = xs[ty + 16 * i][kk];
            #pragma unroll
            for (int j = 0; j < 4; j++) b[j] = ws[kk][tx + 16 * j];
            #pragma unroll
            for (int i = 0; i < 8; i++)
                #pragma unroll
                for (int j = 0; j < 4; j++)
                    acc[i][j] += a[i] * b[j];
        }
        __syncthreads();
    }
    #pragma unroll
    for (int i = 0; i < 8; i++) {
        int gr = rowBase + ty + 16 * i;
        if (gr >= M) continue;
        #pragma unroll
        for (int j = 0; j < 4; j++) {
            int col = tx + 16 * j;
            Y[(size_t)gr * 64 + col] = fmaxf(acc[i][j] + B[col], 0.0f);
        }
    }
}

// ---------------- fused K/Q/V projection + per-relation K/V transform ----------------
// Computes K/Q/V for a 64-row tile; writes Q; transforms K,V per src-relation
// (k~ = (k@A)*P*scale, v~ = v@M) and writes K~/V~ segments directly.
struct KqvRel { const float *A, *Mm, *P; float *Kt, *Vt; };
struct KqvCtx { KqvRel rel[3]; int nrel; };

__global__ void gemm_kqv_trans_kernel(const float* __restrict__ X,
                                      const float* __restrict__ Wk, const float* __restrict__ Wq,
                                      const float* __restrict__ Wv,
                                      const float* __restrict__ bk, const float* __restrict__ bq,
                                      const float* __restrict__ bv,
                                      float* __restrict__ Yq, int M, KqvCtx ctx) {
    // sbuf aliases: GEMM phase -> xs[64][33] + ws[32][192]; epilogue -> Ksm[64*64] + Vsm[64*64]
    __shared__ float sbuf[64 * 33 + 32 * 192];   // 8256 floats
    __shared__ float bs[192];
    __shared__ float As[3][512];   // [d*64 + f*8 + h]
    __shared__ float Ms2[3][512];
    __shared__ float Ps[3][8];
    float* xs = sbuf;                // [64][33]
    float* ws = sbuf + 64 * 33;      // [32][192]

    int tid = threadIdx.x;
    int rowBase = blockIdx.x * 64;

    // load relation transforms
    for (int rr = 0; rr < ctx.nrel; rr++) {
        #pragma unroll
        for (int it = 0; it < 2; it++) {
            int i = tid + it * 256;
            int h = i >> 6, d = (i >> 3) & 7, f = i & 7;
            As[rr][d * 64 + f * 8 + h]  = ctx.rel[rr].A[i];
            Ms2[rr][d * 64 + f * 8 + h] = ctx.rel[rr].Mm[i];
        }
        if (tid < 8) Ps[rr][tid] = ctx.rel[rr].P[tid];
    }
    if (tid < 64) { bs[tid] = bk[tid]; bs[64 + tid] = bq[tid]; bs[128 + tid] = bv[tid]; }

    int tx = tid & 15, ty = tid >> 4;
    float acc[4][12] = {};
    for (int k0 = 0; k0 < 64; k0 += 32) {
        __syncthreads();
        #pragma unroll
        for (int it = 0; it < 8; it++) {
            int idx = tid + it * 256;
            int r = idx >> 5, c = idx & 31;
            int gr = rowBase + r;
            xs[r * 33 + c] = (gr < M) ? X[(size_t)gr * 64 + k0 + c] : 0.0f;
        }
        #pragma unroll
        for (int it = 0; it < 24; it++) {
            int idx = tid + it * 256;
            int kk = idx / 192, c = idx % 192;
            int gk = k0 + kk;
            const float* Wsel = (c < 64) ? Wk : ((c < 128) ? Wq : Wv);
            int cc = c & 63;
            ws[kk * 192 + c] = Wsel[(size_t)gk * 64 + cc];
        }
        __syncthreads();
        #pragma unroll
        for (int kk = 0; kk < 32; kk++) {
            float a[4], b[12];
            #pragma unroll
            for (int i = 0; i < 4; i++) a[i] = xs[(ty + 16 * i) * 33 + kk];
            #pragma unroll
            for (int j = 0; j < 12; j++) b[j] = ws[kk * 192 + tx + 16 * j];
            #pragma unroll
            for (int i = 0; i < 4; i++)
                #pragma unroll
                for (int j = 0; j < 12; j++)
                    acc[i][j] += a[i] * b[j];
        }
    }

    // write Q
    #pragma unroll
    for (int i = 0; i < 4; i++) {
        int gr = rowBase + ty + 16 * i;
        if (gr >= M) continue;
        #pragma unroll
        for (int j = 0; j < 4; j++) {
            int col = tx + 16 * j;
            Yq[(size_t)gr * 64 + col] = acc[i][j + 4] + bs[64 + col];
        }
    }

    // stage K,V tiles in smem (alias over xs/ws)
    __syncthreads();
    float* Ksm = sbuf;               // [64][64]
    float* Vsm = sbuf + 4096;        // [64][64]
    #pragma unroll
    for (int i = 0; i < 4; i++) {
        int row = ty + 16 * i;
        #pragma unroll
        for (int j = 0; j < 4; j++) {
            int col = tx + 16 * j;
            Ksm[row * 64 + col] = acc[i][j]     + bs[col];
            Vsm[row * 64 + col] = acc[i][j + 8] + bs[128 + col];
        }
    }
    __syncthreads();

    // transform + write K~/V~ : 256 threads = 32 (row,head) groups, 2 halves
    int h = tid & 7;
    #pragma unroll
    for (int half = 0; half < 2; half++) {
        int row = (tid >> 3) + 32 * half;
        int node = rowBase + row;
        if (node >= M) continue;
        float k[8], v[8];
        #pragma unroll
        for (int d = 0; d < 8; d++) {
            k[d] = Ksm[row * 64 + h * 8 + d];
            v[d] = Vsm[row * 64 + h * 8 + d];
        }
        #pragma unroll
        for (int rr = 0; rr < 3; rr++) {
            if (rr >= ctx.nrel) break;
            float ps = Ps[rr][h] * 0.35355339059327373f;
            float kt[8], vt[8];
            #pragma unroll
            for (int f = 0; f < 8; f++) {
                float ka = 0.0f, va = 0.0f;
                #pragma unroll
                for (int d = 0; d < 8; d++) {
                    ka += k[d] * As[rr][d * 64 + f * 8 + h];
                    va += v[d] * Ms2[rr][d * 64 + f * 8 + h];
                }
                kt[f] = ka * ps;
                vt[f] = va;
            }
            float4* ko = (float4*)(ctx.rel[rr].Kt + (size_t)node * 64 + h * 8);
            ko[0] = make_float4(kt[0], kt[1], kt[2], kt[3]);
            ko[1] = make_float4(kt[4], kt[5], kt[6], kt[7]);
            float4* vo = (float4*)(ctx.rel[rr].Vt + (size_t)node * 64 + h * 8);
            vo[0] = make_float4(vt[0], vt[1], vt[2], vt[3]);
            vo[1] = make_float4(vt[4], vt[5], vt[6], vt[7]);
        }
    }
}

// ---------------- dst-centric online-softmax attention ----------------
struct AttnRel {
    const float *Kt, *Q, *Vt;
    const int* rowPtr;
    float* acc;
    int Nd;
};
struct AttnCtx {
    AttnRel rel[R_RELS];
    int blkOff[R_RELS + 1];
};

__global__ void attn_kernel(AttnCtx p, const int* __restrict__ srcs) {
    int b = blockIdx.x;
    int r = 0;
    #pragma unroll
    for (int i = 1; i < R_RELS; i++) if (b >= p.blkOff[i]) r = i;
    const AttnRel rc = p.rel[r];
    int tid = threadIdx.x;

    int node = (b - p.blkOff[r]) * 32 + (tid >> 3);
    int h = tid & 7;
    if (node >= rc.Nd) return;

    const float4* qp = (const float4*)(rc.Q + (size_t)node * 64 + h * 8);
    float4 q0 = qp[0], q1 = qp[1];
    float q[8] = {q0.x, q0.y, q0.z, q0.w, q1.x, q1.y, q1.z, q1.w};

    int beg = rc.rowPtr[node];
    int end = rc.rowPtr[node + 1];

    float m = -INFINITY, den = 0.0f;
    float a[8] = {};

    #pragma unroll 2
    for (int j = beg; j < end; j++) {
        int s = __ldg(&srcs[j]);
        const float4* kp = (const float4*)(rc.Kt + (size_t)s * 64 + h * 8);
        float4 k0 = kp[0], k1 = kp[1];
        const float4* vp = (const float4*)(rc.Vt + (size_t)s * 64 + h * 8);
        float4 v0 = vp[0], v1 = vp[1];

        float sc = q[0] * k0.x + q[1] * k0.y + q[2] * k0.z + q[3] * k0.w
                 + q[4] * k1.x + q[5] * k1.y + q[6] * k1.z + q[7] * k1.w;

        float mn = fmaxf(m, sc);
        float cOld = __expf(m - mn);
        float ex = __expf(sc - mn);
        den = den * cOld + ex;
        a[0] = a[0] * cOld + ex * v0.x;
        a[1] = a[1] * cOld + ex * v0.y;
        a[2] = a[2] * cOld + ex * v0.z;
        a[3] = a[3] * cOld + ex * v0.w;
        a[4] = a[4] * cOld + ex * v1.x;
        a[5] = a[5] * cOld + ex * v1.y;
        a[6] = a[6] * cOld + ex * v1.z;
        a[7] = a[7] * cOld + ex * v1.w;
        m = mn;
    }

    float inv = (den > 0.0f) ? 1.0f / den : 0.0f;
    float4* op = (float4*)(rc.acc + (size_t)node * 64 + h * 8);
    op[0] = make_float4(a[0] * inv, a[1] * inv, a[2] * inv, a[3] * inv);
    op[1] = make_float4(a[4] * inv, a[5] * inv, a[6] * inv, a[7] * inv);
}

// ---------------- fused adapter: sum rel outputs -> gelu -> @AW+Ab -> gated residual ----------------
__global__ void adapter_kernel(const float* __restrict__ a0, const float* __restrict__ a1,
                               const float* __restrict__ a2,
                               const float* __restrict__ W, const float* __restrict__ B,
                               const float* __restrict__ skip, int skipIdx,
                               float* __restrict__ h, int M) {
    __shared__ float xs[64][65];
    __shared__ float ws[64][64];
    __shared__ float bs[64];
    int tid = threadIdx.x;
    int rowBase = blockIdx.x * 64;
    #pragma unroll
    for (int it = 0; it < 16; it++) {
        int idx = tid + it * 256;
        int r = idx >> 6, c = idx & 63;
        int node = rowBase + r;
        float v = 0.0f;
        if (node < M) {
            v = a0[(size_t)node * 64 + c];
            if (a1) v += a1[(size_t)node * 64 + c];
            if (a2) v += a2[(size_t)node * 64 + c];
        }
        xs[r][c] = gelu_exact(v);
        ws[r][c] = W[idx];
    }
    if (tid < 64) bs[tid] = B[tid];
    __syncthreads();
    int tx = tid & 15, ty = tid >> 4;
    float acc[4][4] = {};
    #pragma unroll
    for (int k = 0; k < 64; k++) {
        float a[4], b[4];
        #pragma unroll
        for (int i = 0; i < 4; i++) a[i] = xs[ty + 16 * i][k];
        #pragma unroll
        for (int j = 0; j < 4; j++) b[j] = ws[k][tx + 16 * j];
        #pragma unroll
        for (int i = 0; i < 4; i++)
            #pragma unroll
            for (int j = 0; j < 4; j++)
                acc[i][j] += a[i] * b[j];
    }
    float g = 1.0f / (1.0f + __expf(-skip[skipIdx]));
    #pragma unroll
    for (int i = 0; i < 4; i++) {
        int gr = rowBase + ty + 16 * i;
        if (gr >= M) continue;
        #pragma unroll
        for (int j = 0; j < 4; j++) {
            int col = tx + 16 * j;
            size_t o = (size_t)gr * 64 + col;
            h[o] = g * (acc[i][j] + bs[col]) + (1.0f - g) * h[o];
        }
    }
}

// ---------------- final head ----------------
__global__ void out_kernel(const float* __restrict__ h, const float* __restrict__ Wo,
                           const float* __restrict__ bo, float* __restrict__ y, int n) {
    __shared__ float ws[256];
    __shared__ float bs[4];
    if (threadIdx.x < 256) ws[threadIdx.x] = Wo[threadIdx.x];
    if (threadIdx.x < 4) bs[threadIdx.x] = bo[threadIdx.x];
    __syncthreads();
    int node = blockIdx.x * blockDim.x + threadIdx.x;
    if (node >= n) return;
    const float4* hp = (const float4*)(h + (size_t)node * 64);
    float a0 = bs[0], a1 = bs[1], a2 = bs[2], a3 = bs[3];
    #pragma unroll
    for (int i = 0; i < 16; i++) {
        float4 hv = hp[i];
        const float* w = ws + 16 * i;
        a0 += hv.x * w[0]  + hv.y * w[4]  + hv.z * w[8]  + hv.w * w[12];
        a1 += hv.x * w[1]  + hv.y * w[5]  + hv.z * w[9]  + hv.w * w[13];
        a2 += hv.x * w[2]  + hv.y * w[6]  + hv.z * w[10] + hv.w * w[14];
        a3 += hv.x * w[3]  + hv.y * w[7]  + hv.z * w[11] + hv.w * w[15];
    }
    ((float4*)y)[node] = make_float4(a0, a1, a2, a3);
}

// ---------------- host launcher ----------------
static inline int cdiv(int a, int b) { return (a + b - 1) / b; }

extern "C" void kernel_launch(void* const* d_in, const int* in_sizes, int n_in,
                              void* d_out, int out_size) {
    (void)n_in; (void)out_size;

    const float* x[T_TYPES]   = {(const float*)d_in[0], (const float*)d_in[1],
                                 (const float*)d_in[2], (const float*)d_in[3]};
    const float* Win[T_TYPES] = {(const float*)d_in[4], (const float*)d_in[6],
                                 (const float*)d_in[8], (const float*)d_in[10]};
    const float* bin[T_TYPES] = {(const float*)d_in[5], (const float*)d_in[7],
                                 (const float*)d_in[9], (const float*)d_in[11]};

    const float *KW, *Kb, *QW, *Qb, *VW, *Vb, *AW, *Ab;
    if (in_sizes[13] > 4096) {
        KW = (const float*)d_in[12]; QW = (const float*)d_in[13];
        VW = (const float*)d_in[14]; AW = (const float*)d_in[15];
        Kb = (const float*)d_in[16]; Qb = (const float*)d_in[17];
        Vb = (const float*)d_in[18]; Ab = (const float*)d_in[19];
    } else {
        KW = (const float*)d_in[12]; Kb = (const float*)d_in[13];
        QW = (const float*)d_in[14]; Qb = (const float*)d_in[15];
        VW = (const float*)d_in[16]; Vb = (const float*)d_in[17];
        AW = (const float*)d_in[18]; Ab = (const float*)d_in[19];
    }
    const float* skip  = (const float*)d_in[20];
    const float* A_rel = (const float*)d_in[21];
    const float* M_rel = (const float*)d_in[22];
    const float* P_rel = (const float*)d_in[23];
    const float* W_out = (const float*)d_in[24];
    const float* b_out = (const float*)d_in[25];
    const int* ei[R_RELS] = {(const int*)d_in[26], (const int*)d_in[27], (const int*)d_in[28],
                             (const int*)d_in[29], (const int*)d_in[30], (const int*)d_in[31]};

    float *hB, *qB, *ktB, *vtB, *accB;
    unsigned* cntB;
    int *rowB, *curB, *bsumB, *srcsB;
    cudaGetSymbolAddress((void**)&hB,   g_h);
    cudaGetSymbolAddress((void**)&qB,   g_Q);
    cudaGetSymbolAddress((void**)&ktB,  g_Kt);
    cudaGetSymbolAddress((void**)&vtB,  g_Vt);
    cudaGetSymbolAddress((void**)&accB, g_acc);
    cudaGetSymbolAddress((void**)&cntB, g_cnt);
    cudaGetSymbolAddress((void**)&rowB, g_rowptr);
    cudaGetSymbolAddress((void**)&curB, g_cur);
    cudaGetSymbolAddress((void**)&bsumB, g_bsum);
    cudaGetSymbolAddress((void**)&srcsB, g_srcs);

    // ---- CSR build (once; edge lists constant across layers) ----
    fill4_u32<<<1024, 256>>>((uint4*)cntB, 0u, NDSUM / 4);
    for (int r = 0; r < R_RELS; r++) {
        count_kernel<<<cdiv(E_[r], 256), 256>>>(ei[r] + E_[r], cntB + CUMND_[r], E_[r]);
    }
    int nScanBlocks = cdiv(NDSUM, 2048);
    scan1_kernel<<<nScanBlocks, 256>>>(cntB, rowB, bsumB, NDSUM);
    scan2_kernel<<<1, 512>>>(bsumB, nScanBlocks);
    scan3_kernel<<<cdiv(NDSUM, 256), 256>>>(rowB, curB, bsumB, NDSUM, ESUM);
    for (int r = 0; r < R_RELS; r++) {
        scatter_kernel<<<cdiv(E_[r], 256), 256>>>(ei[r], ei[r] + E_[r],
                                                  curB + CUMND_[r], srcsB, E_[r]);
    }

    // ---- input projections ----
    for (int t = 0; t < T_TYPES; t++) {
        gemm_in_kernel<<<cdiv(N_[t], 128), 256>>>(
            x[t], Win[t], bin[t], hB + (size_t)OFF_[t] * HID, N_[t], F_[t]);
    }

    // relations for which each type is the source
    static const int relsBySrc[T_TYPES][3] = {{0, -1, -1}, {1, 2, 4}, {3, -1, -1}, {5, -1, -1}};
    static const int nRelsBySrc[T_TYPES]   = {1, 3, 1, 1};

    for (int l = 0; l < LAYERS; l++) {
        // fused K/Q/V projections + per-relation transform per type
        for (int t = 0; t < T_TYPES; t++) {
            int base = l * T_TYPES + t;
            KqvCtx ctx;
            ctx.nrel = nRelsBySrc[t];
            for (int i = 0; i < 3; i++) {
                int r = relsBySrc[t][i];
                if (r < 0) { ctx.rel[i] = {nullptr, nullptr, nullptr, nullptr, nullptr}; continue; }
                int relBase = l * R_RELS + r;
                ctx.rel[i].A  = A_rel + (size_t)relBase * 512;
                ctx.rel[i].Mm = M_rel + (size_t)relBase * 512;
                ctx.rel[i].P  = P_rel + (size_t)relBase * 8;
                ctx.rel[i].Kt = ktB + (size_t)CUMSRC_[r] * HID;
                ctx.rel[i].Vt = vtB + (size_t)CUMSRC_[r] * HID;
            }
            gemm_kqv_trans_kernel<<<cdiv(N_[t], 64), 256>>>(
                hB + (size_t)OFF_[t] * HID,
                KW + (size_t)base * 4096, QW + (size_t)base * 4096, VW + (size_t)base * 4096,
                Kb + (size_t)base * 64,   Qb + (size_t)base * 64,   Vb + (size_t)base * 64,
                qB + (size_t)OFF_[t] * HID, N_[t], ctx);
        }

        // attention over all relations, one launch
        AttnCtx p;
        for (int r = 0; r < R_RELS; r++) {
            int d = RD_[r];
            p.rel[r].Kt = ktB + (size_t)CUMSRC_[r] * HID;
            p.rel[r].Q  = qB + (size_t)OFF_[d] * HID;
            p.rel[r].Vt = vtB + (size_t)CUMSRC_[r] * HID;
            p.rel[r].rowPtr = rowB + CUMND_[r];
            p.rel[r].acc = accB + (size_t)CUMND_[r] * HID;
            p.rel[r].Nd = N_[d];
        }
        for (int i = 0; i <= R_RELS; i++) p.blkOff[i] = ABLK_[i];
        attn_kernel<<<ATTN_BLOCKS, 256>>>(p, srcsB);

        // fused adapter per type; rels by dst type: author<-{1}, paper<-{0,3,5}, term<-{2}, conf<-{4}
        static const int relsByType[T_TYPES][3] = {{1, -1, -1}, {0, 3, 5}, {2, -1, -1}, {4, -1, -1}};
        for (int t = 0; t < T_TYPES; t++) {
            int base = l * T_TYPES + t;
            const float *a0 = accB + (size_t)CUMND_[relsByType[t][0]] * HID;
            const float *a1 = (relsByType[t][1] >= 0) ? accB + (size_t)CUMND_[relsByType[t][1]] * HID : nullptr;
            const float *a2 = (relsByType[t][2] >= 0) ? accB + (size_t)CUMND_[relsByType[t][2]] * HID : nullptr;
            adapter_kernel<<<cdiv(N_[t], 64), 256>>>(
                a0, a1, a2,
                AW + (size_t)base * 4096, Ab + (size_t)base * 64,
                skip, base,
                hB + (size_t)OFF_[t] * HID, N_[t]);
        }
    }

    // final head on author nodes
    out_kernel<<<cdiv(N_[0], 256), 256>>>(hB, W_out, b_out, (float*)d_out, N_[0]);
}

// round 7
// speedup vs baseline: 1.0835x; 1.0835x over previous
#include <cuda_runtime.h>
#include <cuda_fp16.h>
#include <math.h>

// ---------------- problem constants ----------------
#define T_TYPES 4
#define R_RELS 6
#define HID 64
#define HEADS 8
#define DH 8
#define LAYERS 2
#define OUT_DIM 4

static const int N_[T_TYPES]   = {100000, 200000, 20000, 2000};
static const int F_[T_TYPES]   = {334, 512, 128, 128};
static const int OFF_[T_TYPES] = {0, 100000, 300000, 320000};
#define NTOT 322000
static const int E_[R_RELS]  = {800000, 800000, 1000000, 1000000, 200000, 200000};
static const int RS_[R_RELS] = {0, 1, 1, 2, 1, 3};   // src type
static const int RD_[R_RELS] = {1, 0, 2, 1, 3, 1};   // dst type

// per-relation dst segmentation (cumulative)
static const int CUMND_[R_RELS + 1] = {0, 200000, 300000, 320000, 520000, 522000, 722000};
#define NDSUM 722000
// per-relation src segmentation (cumulative)
static const int CUMSRC_[R_RELS + 1] = {0, 100000, 300000, 500000, 520000, 720000, 722000};
#define SRCSUM 722000
#define ESUM  4000000

// attention: blocks per relation (32 dst nodes / block)
static const int ABLK_[R_RELS + 1] = {0, 6250, 9375, 10000, 16250, 16313, 22563};
#define ATTN_BLOCKS 22563
// transform: blocks per relation (32 src nodes / block)
static const int TBLK_[R_RELS + 1] = {0, 3125, 9375, 15625, 16250, 22500, 22563};
#define TRANS_BLOCKS 22563

// ---------------- device scratch (static, no allocation) ----------------
__device__ float    g_h[NTOT * HID];
__device__ float    g_K[NTOT * HID];
__device__ float    g_Q[NTOT * HID];
__device__ float    g_V[NTOT * HID];
__device__ __half   g_KVt[(size_t)SRCSUM * 128];  // interleaved fp16: node*128 + h*16 -> [k0..k7, v0..v7]
__device__ float    g_acc[NDSUM * HID];           // per-relation normalized attention output
__device__ unsigned g_cnt[NDSUM];
__device__ int      g_rowptr[NDSUM + 1];
__device__ int      g_cur[NDSUM];
__device__ int      g_bsum[512];
__device__ int      g_srcs[ESUM];

// ---------------- helpers ----------------
__device__ __forceinline__ float gelu_exact(float x) {
    return 0.5f * x * (1.0f + erff(x * 0.70710678118654752f));
}

__global__ void fill4_u32(uint4* p, unsigned v, int n4) {
    int i = blockIdx.x * blockDim.x + threadIdx.x;
    uint4 val = make_uint4(v, v, v, v);
    for (; i < n4; i += gridDim.x * blockDim.x) p[i] = val;
}

// ---------------- CSR build ----------------
__global__ void count_kernel(const int* __restrict__ dst, unsigned* __restrict__ cnt, int E) {
    int e = blockIdx.x * blockDim.x + threadIdx.x;
    if (e < E) atomicAdd(&cnt[dst[e]], 1u);
}

__global__ void scan1_kernel(const unsigned* __restrict__ cnt, int* __restrict__ row,
                             int* __restrict__ bsum, int n) {
    __shared__ int sm[256];
    int tid = threadIdx.x;
    int base = blockIdx.x * 2048 + tid * 8;
    int vals[8];
    int s = 0;
    #pragma unroll
    for (int i = 0; i < 8; i++) {
        int idx = base + i;
        int t = (idx < n) ? (int)cnt[idx] : 0;
        vals[i] = s;
        s += t;
    }
    sm[tid] = s;
    __syncthreads();
    #pragma unroll
    for (int off = 1; off < 256; off <<= 1) {
        int t = (tid >= off) ? sm[tid - off] : 0;
        __syncthreads();
        sm[tid] += t;
        __syncthreads();
    }
    int excl = sm[tid] - s;
    if (tid == 255) bsum[blockIdx.x] = sm[255];
    #pragma unroll
    for (int i = 0; i < 8; i++) {
        int idx = base + i;
        if (idx < n) row[idx] = excl + vals[i];
    }
}

__global__ void scan2_kernel(int* __restrict__ bsum, int nb) {
    __shared__ int sm[512];
    int tid = threadIdx.x;
    int v = (tid < nb) ? bsum[tid] : 0;
    sm[tid] = v;
    __syncthreads();
    #pragma unroll
    for (int off = 1; off < 512; off <<= 1) {
        int t = (tid >= off) ? sm[tid - off] : 0;
        __syncthreads();
        sm[tid] += t;
        __syncthreads();
    }
    if (tid < nb) bsum[tid] = sm[tid] - v;
}

__global__ void scan3_kernel(int* __restrict__ row, int* __restrict__ cur,
                             const int* __restrict__ bsum, int n, int total) {
    int idx = blockIdx.x * blockDim.x + threadIdx.x;
    if (idx < n) {
        int v = row[idx] + bsum[idx >> 11];
        row[idx] = v;
        cur[idx] = v;
    }
    if (idx == 0) row[n] = total;
}

__global__ void scatter_kernel(const int* __restrict__ src, const int* __restrict__ dst,
                               int* __restrict__ cur, int* __restrict__ srcs, int E) {
    int e = blockIdx.x * blockDim.x + threadIdx.x;
    if (e >= E) return;
    int pos = atomicAdd(&cur[dst[e]], 1);
    srcs[pos] = src[e];
}

// ---------------- input projection GEMM: Y = relu(X[M,K] @ W[K,64] + B) ----------------
__global__ void gemm_in_kernel(const float* __restrict__ X, const float* __restrict__ W,
                               const float* __restrict__ B, float* __restrict__ Y,
                               int M, int K) {
    __shared__ float xs[128][33];
    __shared__ float ws[32][64];
    int tid = threadIdx.x;
    int tx = tid & 15, ty = tid >> 4;
    int rowBase = blockIdx.x * 128;
    float acc[8][4] = {};
    for (int k0 = 0; k0 < K; k0 += 32) {
        #pragma unroll
        for (int it = 0; it < 16; it++) {
            int idx = tid + it * 256;
            int r = idx >> 5, c = idx & 31;
            int gr = rowBase + r, gc = k0 + c;
            xs[r][c] = (gr < M && gc < K) ? X[(size_t)gr * K + gc] : 0.0f;
        }
        #pragma unroll
        for (int it = 0; it < 8; it++) {
            int idx = tid + it * 256;
            int kk = idx >> 6, c = idx & 63;
            int gk = k0 + kk;
            ws[kk][c] = (gk < K) ? W[(size_t)gk * 64 + c] : 0.0f;
        }
        __syncthreads();
        #pragma unroll
        for (int kk = 0; kk < 32; kk++) {
            float a[8], b[4];
            #pragma unroll
            for (int i = 0; i < 8; i++) a[i] = xs[ty + 16 * i][kk];
            #pragma unroll
            for (int j = 0; j < 4; j++) b[j] = ws[kk][tx + 16 * j];
            #pragma unroll
            for (int i = 0; i < 8; i++)
                #pragma unroll
                for (int j = 0; j < 4; j++)
                    acc[i][j] += a[i] * b[j];
        }
        __syncthreads();
    }
    #pragma unroll
    for (int i = 0; i < 8; i++) {
        int gr = rowBase + ty + 16 * i;
        if (gr >= M) continue;
        #pragma unroll
        for (int j = 0; j < 4; j++) {
            int col = tx + 16 * j;
            Y[(size_t)gr * 64 + col] = fmaxf(acc[i][j] + B[col], 0.0f);
        }
    }
}

// ---------------- fused K/Q/V projection (K=64) ----------------
__global__ void gemm_kqv_kernel(const float* __restrict__ X,
                                const float* __restrict__ Wk, const float* __restrict__ Wq,
                                const float* __restrict__ Wv,
                                const float* __restrict__ bk, const float* __restrict__ bq,
                                const float* __restrict__ bv,
                                float* __restrict__ Yk, float* __restrict__ Yq,
                                float* __restrict__ Yv, int M) {
    __shared__ float xs[64][65];
    __shared__ float ws[64][192];
    __shared__ float bs[192];
    int tid = threadIdx.x;
    int rowBase = blockIdx.x * 64;
    #pragma unroll
    for (int it = 0; it < 16; it++) {
        int idx = tid + it * 256;
        int r = idx >> 6, c = idx & 63;
        int gr = rowBase + r;
        xs[r][c] = (gr < M) ? X[(size_t)gr * 64 + c] : 0.0f;
        ws[r][c]       = Wk[idx];
        ws[r][64 + c]  = Wq[idx];
        ws[r][128 + c] = Wv[idx];
    }
    if (tid < 64) { bs[tid] = bk[tid]; bs[64 + tid] = bq[tid]; bs[128 + tid] = bv[tid]; }
    __syncthreads();
    int tx = tid & 15, ty = tid >> 4;
    float acc[4][12] = {};
    #pragma unroll
    for (int k = 0; k < 64; k++) {
        float a[4], b[12];
        #pragma unroll
        for (int i = 0; i < 4; i++) a[i] = xs[ty + 16 * i][k];
        #pragma unroll
        for (int j = 0; j < 12; j++) b[j] = ws[k][tx + 16 * j];
        #pragma unroll
        for (int i = 0; i < 4; i++)
            #pragma unroll
            for (int j = 0; j < 12; j++)
                acc[i][j] += a[i] * b[j];
    }
    #pragma unroll
    for (int i = 0; i < 4; i++) {
        int gr = rowBase + ty + 16 * i;
        if (gr >= M) continue;
        #pragma unroll
        for (int j = 0; j < 4; j++) {
            int col = tx + 16 * j;
            Yk[(size_t)gr * 64 + col] = acc[i][j]     + bs[col];
            Yq[(size_t)gr * 64 + col] = acc[i][j + 4] + bs[64 + col];
            Yv[(size_t)gr * 64 + col] = acc[i][j + 8] + bs[128 + col];
        }
    }
}

// ---------------- per-relation K/V transform -> interleaved fp16 ----------------
struct TransRel {
    const float *K, *V, *A, *Mm, *P;
    __half* KVt;
    int Nsrc;
};
struct TransCtx {
    TransRel rel[R_RELS];
    int blkOff[R_RELS + 1];
};

__global__ void transform_kernel(TransCtx p) {
    __shared__ float As[512];   // [d*64 + f*8 + h]
    __shared__ float Ms[512];
    __shared__ float Ps[8];
    int b = blockIdx.x;
    int r = 0;
    #pragma unroll
    for (int i = 1; i < R_RELS; i++) if (b >= p.blkOff[i]) r = i;
    const TransRel rc = p.rel[r];
    int tid = threadIdx.x;
    #pragma unroll
    for (int it = 0; it < 2; it++) {
        int i = tid + it * 256;
        int h = i >> 6, d = (i >> 3) & 7, f = i & 7;
        As[d * 64 + f * 8 + h] = rc.A[i];
        Ms[d * 64 + f * 8 + h] = rc.Mm[i];
    }
    if (tid < 8) Ps[tid] = rc.P[tid];
    __syncthreads();

    int node = (b - p.blkOff[r]) * 32 + (tid >> 3);
    int h = tid & 7;
    if (node >= rc.Nsrc) return;

    const float4* kp = (const float4*)(rc.K + (size_t)node * 64 + h * 8);
    float4 k0 = kp[0], k1 = kp[1];
    float k[8] = {k0.x, k0.y, k0.z, k0.w, k1.x, k1.y, k1.z, k1.w};
    const float4* vp = (const float4*)(rc.V + (size_t)node * 64 + h * 8);
    float4 v0 = vp[0], v1 = vp[1];
    float v[8] = {v0.x, v0.y, v0.z, v0.w, v1.x, v1.y, v1.z, v1.w};

    float ps = Ps[h] * 0.35355339059327373f;
    float kt[8], vt[8];
    #pragma unroll
    for (int f = 0; f < 8; f++) {
        float ka = 0.0f, va = 0.0f;
        #pragma unroll
        for (int d = 0; d < 8; d++) {
            ka += k[d] * As[d * 64 + f * 8 + h];
            va += v[d] * Ms[d * 64 + f * 8 + h];
        }
        kt[f] = ka * ps;
        vt[f] = va;
    }
    // pack to fp16, interleaved [k0..k7, v0..v7] at node*128 + h*16
    __half2 pk[4], pv[4];
    #pragma unroll
    for (int i = 0; i < 4; i++) {
        pk[i] = __float22half2_rn(make_float2(kt[2 * i], kt[2 * i + 1]));
        pv[i] = __float22half2_rn(make_float2(vt[2 * i], vt[2 * i + 1]));
    }
    uint4* out = (uint4*)(rc.KVt + (size_t)node * 128 + h * 16);
    out[0] = *(uint4*)pk;
    out[1] = *(uint4*)pv;
}

// ---------------- dst-centric online-softmax attention (fp16 gather) ----------------
struct AttnRel {
    const __half* KVt;
    const float* Q;
    const int* rowPtr;
    float* acc;
    int Nd;
};
struct AttnCtx {
    AttnRel rel[R_RELS];
    int blkOff[R_RELS + 1];
};

__global__ void attn_kernel(AttnCtx p, const int* __restrict__ srcs) {
    int b = blockIdx.x;
    int r = 0;
    #pragma unroll
    for (int i = 1; i < R_RELS; i++) if (b >= p.blkOff[i]) r = i;
    const AttnRel rc = p.rel[r];
    int tid = threadIdx.x;

    int node = (b - p.blkOff[r]) * 32 + (tid >> 3);
    int h = tid & 7;
    if (node >= rc.Nd) return;

    const float4* qp = (const float4*)(rc.Q + (size_t)node * 64 + h * 8);
    float4 q0 = qp[0], q1 = qp[1];
    float q[8] = {q0.x, q0.y, q0.z, q0.w, q1.x, q1.y, q1.z, q1.w};

    int beg = rc.rowPtr[node];
    int end = rc.rowPtr[node + 1];

    float m = -INFINITY, den = 0.0f;
    float a[8] = {};

    #pragma unroll 2
    for (int j = beg; j < end; j++) {
        int s = __ldg(&srcs[j]);
        const uint4* kvp = (const uint4*)(rc.KVt + (size_t)s * 128 + h * 16);
        uint4 kw = kvp[0];
        uint4 vw = kvp[1];
        const __half2* kh = (const __half2*)&kw;
        const __half2* vh = (const __half2*)&vw;
        float2 kf0 = __half22float2(kh[0]), kf1 = __half22float2(kh[1]);
        float2 kf2 = __half22float2(kh[2]), kf3 = __half22float2(kh[3]);
        float2 vf0 = __half22float2(vh[0]), vf1 = __half22float2(vh[1]);
        float2 vf2 = __half22float2(vh[2]), vf3 = __half22float2(vh[3]);

        float sc = q[0] * kf0.x + q[1] * kf0.y + q[2] * kf1.x + q[3] * kf1.y
                 + q[4] * kf2.x + q[5] * kf2.y + q[6] * kf3.x + q[7] * kf3.y;

        float mn = fmaxf(m, sc);
        float cOld = __expf(m - mn);
        float ex = __expf(sc - mn);
        den = den * cOld + ex;
        a[0] = a[0] * cOld + ex * vf0.x;
        a[1] = a[1] * cOld + ex * vf0.y;
        a[2] = a[2] * cOld + ex * vf1.x;
        a[3] = a[3] * cOld + ex * vf1.y;
        a[4] = a[4] * cOld + ex * vf2.x;
        a[5] = a[5] * cOld + ex * vf2.y;
        a[6] = a[6] * cOld + ex * vf3.x;
        a[7] = a[7] * cOld + ex * vf3.y;
        m = mn;
    }

    float inv = (den > 0.0f) ? 1.0f / den : 0.0f;
    float4* op = (float4*)(rc.acc + (size_t)node * 64 + h * 8);
    op[0] = make_float4(a[0] * inv, a[1] * inv, a[2] * inv, a[3] * inv);
    op[1] = make_float4(a[4] * inv, a[5] * inv, a[6] * inv, a[7] * inv);
}

// ---------------- fused adapter: sum rel outputs -> gelu -> @AW+Ab -> gated residual ----------------
__global__ void adapter_kernel(const float* __restrict__ a0, const float* __restrict__ a1,
                               const float* __restrict__ a2,
                               const float* __restrict__ W, const float* __restrict__ B,
                               const float* __restrict__ skip, int skipIdx,
                               float* __restrict__ h, int M) {
    __shared__ float xs[64][65];
    __shared__ float ws[64][64];
    __shared__ float bs[64];
    int tid = threadIdx.x;
    int rowBase = blockIdx.x * 64;
    #pragma unroll
    for (int it = 0; it < 16; it++) {
        int idx = tid + it * 256;
        int r = idx >> 6, c = idx & 63;
        int node = rowBase + r;
        float v = 0.0f;
        if (node < M) {
            v = a0[(size_t)node * 64 + c];
            if (a1) v += a1[(size_t)node * 64 + c];
            if (a2) v += a2[(size_t)node * 64 + c];
        }
        xs[r][c] = gelu_exact(v);
        ws[r][c] = W[idx];
    }
    if (tid < 64) bs[tid] = B[tid];
    __syncthreads();
    int tx = tid & 15, ty = tid >> 4;
    float acc[4][4] = {};
    #pragma unroll
    for (int k = 0; k < 64; k++) {
        float a[4], b[4];
        #pragma unroll
        for (int i = 0; i < 4; i++) a[i] = xs[ty + 16 * i][k];
        #pragma unroll
        for (int j = 0; j < 4; j++) b[j] = ws[k][tx + 16 * j];
        #pragma unroll
        for (int i = 0; i < 4; i++)
            #pragma unroll
            for (int j = 0; j < 4; j++)
                acc[i][j] += a[i] * b[j];
    }
    float g = 1.0f / (1.0f + __expf(-skip[skipIdx]));
    #pragma unroll
    for (int i = 0; i < 4; i++) {
        int gr = rowBase + ty + 16 * i;
        if (gr >= M) continue;
        #pragma unroll
        for (int j = 0; j < 4; j++) {
            int col = tx + 16 * j;
            size_t o = (size_t)gr * 64 + col;
            h[o] = g * (acc[i][j] + bs[col]) + (1.0f - g) * h[o];
        }
    }
}

// ---------------- final head ----------------
__global__ void out_kernel(const float* __restrict__ h, const float* __restrict__ Wo,
                           const float* __restrict__ bo, float* __restrict__ y, int n) {
    __shared__ float ws[256];
    __shared__ float bs[4];
    if (threadIdx.x < 256) ws[threadIdx.x] = Wo[threadIdx.x];
    if (threadIdx.x < 4) bs[threadIdx.x] = bo[threadIdx.x];
    __syncthreads();
    int node = blockIdx.x * blockDim.x + threadIdx.x;
    if (node >= n) return;
    const float4* hp = (const float4*)(h + (size_t)node * 64);
    float a0 = bs[0], a1 = bs[1], a2 = bs[2], a3 = bs[3];
    #pragma unroll
    for (int i = 0; i < 16; i++) {
        float4 hv = hp[i];
        const float* w = ws + 16 * i;
        a0 += hv.x * w[0]  + hv.y * w[4]  + hv.z * w[8]  + hv.w * w[12];
        a1 += hv.x * w[1]  + hv.y * w[5]  + hv.z * w[9]  + hv.w * w[13];
        a2 += hv.x * w[2]  + hv.y * w[6]  + hv.z * w[10] + hv.w * w[14];
        a3 += hv.x * w[3]  + hv.y * w[7]  + hv.z * w[11] + hv.w * w[15];
    }
    ((float4*)y)[node] = make_float4(a0, a1, a2, a3);
}

// ---------------- host launcher ----------------
static inline int cdiv(int a, int b) { return (a + b - 1) / b; }

extern "C" void kernel_launch(void* const* d_in, const int* in_sizes, int n_in,
                              void* d_out, int out_size) {
    (void)n_in; (void)out_size;

    const float* x[T_TYPES]   = {(const float*)d_in[0], (const float*)d_in[1],
                                 (const float*)d_in[2], (const float*)d_in[3]};
    const float* Win[T_TYPES] = {(const float*)d_in[4], (const float*)d_in[6],
                                 (const float*)d_in[8], (const float*)d_in[10]};
    const float* bin[T_TYPES] = {(const float*)d_in[5], (const float*)d_in[7],
                                 (const float*)d_in[9], (const float*)d_in[11]};

    const float *KW, *Kb, *QW, *Qb, *VW, *Vb, *AW, *Ab;
    if (in_sizes[13] > 4096) {
        KW = (const float*)d_in[12]; QW = (const float*)d_in[13];
        VW = (const float*)d_in[14]; AW = (const float*)d_in[15];
        Kb = (const float*)d_in[16]; Qb = (const float*)d_in[17];
        Vb = (const float*)d_in[18]; Ab = (const float*)d_in[19];
    } else {
        KW = (const float*)d_in[12]; Kb = (const float*)d_in[13];
        QW = (const float*)d_in[14]; Qb = (const float*)d_in[15];
        VW = (const float*)d_in[16]; Vb = (const float*)d_in[17];
        AW = (const float*)d_in[18]; Ab = (const float*)d_in[19];
    }
    const float* skip  = (const float*)d_in[20];
    const float* A_rel = (const float*)d_in[21];
    const float* M_rel = (const float*)d_in[22];
    const float* P_rel = (const float*)d_in[23];
    const float* W_out = (const float*)d_in[24];
    const float* b_out = (const float*)d_in[25];
    const int* ei[R_RELS] = {(const int*)d_in[26], (const int*)d_in[27], (const int*)d_in[28],
                             (const int*)d_in[29], (const int*)d_in[30], (const int*)d_in[31]};

    float *hB, *kB, *qB, *vB, *accB;
    __half* kvtB;
    unsigned* cntB;
    int *rowB, *curB, *bsumB, *srcsB;
    cudaGetSymbolAddress((void**)&hB,   g_h);
    cudaGetSymbolAddress((void**)&kB,   g_K);
    cudaGetSymbolAddress((void**)&qB,   g_Q);
    cudaGetSymbolAddress((void**)&vB,   g_V);
    cudaGetSymbolAddress((void**)&kvtB, g_KVt);
    cudaGetSymbolAddress((void**)&accB, g_acc);
    cudaGetSymbolAddress((void**)&cntB, g_cnt);
    cudaGetSymbolAddress((void**)&rowB, g_rowptr);
    cudaGetSymbolAddress((void**)&curB, g_cur);
    cudaGetSymbolAddress((void**)&bsumB, g_bsum);
    cudaGetSymbolAddress((void**)&srcsB, g_srcs);

    // ---- CSR build (once; edge lists constant across layers) ----
    fill4_u32<<<1024, 256>>>((uint4*)cntB, 0u, NDSUM / 4);
    for (int r = 0; r < R_RELS; r++) {
        count_kernel<<<cdiv(E_[r], 256), 256>>>(ei[r] + E_[r], cntB + CUMND_[r], E_[r]);
    }
    int nScanBlocks = cdiv(NDSUM, 2048);
    scan1_kernel<<<nScanBlocks, 256>>>(cntB, rowB, bsumB, NDSUM);
    scan2_kernel<<<1, 512>>>(bsumB, nScanBlocks);
    scan3_kernel<<<cdiv(NDSUM, 256), 256>>>(rowB, curB, bsumB, NDSUM, ESUM);
    for (int r = 0; r < R_RELS; r++) {
        scatter_kernel<<<cdiv(E_[r], 256), 256>>>(ei[r], ei[r] + E_[r],
                                                  curB + CUMND_[r], srcsB, E_[r]);
    }

    // ---- input projections ----
    for (int t = 0; t < T_TYPES; t++) {
        gemm_in_kernel<<<cdiv(N_[t], 128), 256>>>(
            x[t], Win[t], bin[t], hB + (size_t)OFF_[t] * HID, N_[t], F_[t]);
    }

    for (int l = 0; l < LAYERS; l++) {
        // fused K/Q/V projections per type
        for (int t = 0; t < T_TYPES; t++) {
            int base = l * T_TYPES + t;
            gemm_kqv_kernel<<<cdiv(N_[t], 64), 256>>>(
                hB + (size_t)OFF_[t] * HID,
                KW + (size_t)base * 4096, QW + (size_t)base * 4096, VW + (size_t)base * 4096,
                Kb + (size_t)base * 64,   Qb + (size_t)base * 64,   Vb + (size_t)base * 64,
                kB + (size_t)OFF_[t] * HID, qB + (size_t)OFF_[t] * HID, vB + (size_t)OFF_[t] * HID,
                N_[t]);
        }

        // per-relation K/V transform -> interleaved fp16
        TransCtx tp;
        for (int r = 0; r < R_RELS; r++) {
            int s = RS_[r];
            int relBase = l * R_RELS + r;
            tp.rel[r].K  = kB + (size_t)OFF_[s] * HID;
            tp.rel[r].V  = vB + (size_t)OFF_[s] * HID;
            tp.rel[r].A  = A_rel + (size_t)relBase * 512;
            tp.rel[r].Mm = M_rel + (size_t)relBase * 512;
            tp.rel[r].P  = P_rel + (size_t)relBase * 8;
            tp.rel[r].KVt = kvtB + (size_t)CUMSRC_[r] * 128;
            tp.rel[r].Nsrc = N_[s];
        }
        for (int i = 0; i <= R_RELS; i++) tp.blkOff[i] = TBLK_[i];
        transform_kernel<<<TRANS_BLOCKS, 256>>>(tp);

        // attention over all relations, one launch
        AttnCtx p;
        for (int r = 0; r < R_RELS; r++) {
            int d = RD_[r];
            p.rel[r].KVt = kvtB + (size_t)CUMSRC_[r] * 128;
            p.rel[r].Q   = qB + (size_t)OFF_[d] * HID;
            p.rel[r].rowPtr = rowB + CUMND_[r];
            p.rel[r].acc = accB + (size_t)CUMND_[r] * HID;
            p.rel[r].Nd = N_[d];
        }
        for (int i = 0; i <= R_RELS; i++) p.blkOff[i] = ABLK_[i];
        attn_kernel<<<ATTN_BLOCKS, 256>>>(p, srcsB);

        // fused adapter per type; rels by dst type: author<-{1}, paper<-{0,3,5}, term<-{2}, conf<-{4}
        static const int relsByType[T_TYPES][3] = {{1, -1, -1}, {0, 3, 5}, {2, -1, -1}, {4, -1, -1}};
        for (int t = 0; t < T_TYPES; t++) {
            int base = l * T_TYPES + t;
            const float *a0 = accB + (size_t)CUMND_[relsByType[t][0]] * HID;
            const float *a1 = (relsByType[t][1] >= 0) ? accB + (size_t)CUMND_[relsByType[t][1]] * HID : nullptr;
            const float *a2 = (relsByType[t][2] >= 0) ? accB + (size_t)CUMND_[relsByType[t][2]] * HID : nullptr;
            adapter_kernel<<<cdiv(N_[t], 64), 256>>>(
                a0, a1, a2,
                AW + (size_t)base * 4096, Ab + (size_t)base * 64,
                skip, base,
                hB + (size_t)OFF_[t] * HID, N_[t]);
        }
    }

    // final head on author nodes
    out_kernel<<<cdiv(N_[0], 256), 256>>>(hB, W_out, b_out, (float*)d_out, N_[0]);
}

// round 8
// speedup vs baseline: 1.4430x; 1.3317x over previous
#include <cuda_runtime.h>
#include <cuda_fp16.h>
#include <math.h>

// ---------------- problem constants ----------------
#define T_TYPES 4
#define R_RELS 6
#define HID 64
#define HEADS 8
#define DH 8
#define LAYERS 2
#define OUT_DIM 4

static const int N_[T_TYPES]   = {100000, 200000, 20000, 2000};
static const int F_[T_TYPES]   = {334, 512, 128, 128};
static const int OFF_[T_TYPES] = {0, 100000, 300000, 320000};
#define NTOT 322000
static const int E_[R_RELS]  = {800000, 800000, 1000000, 1000000, 200000, 200000};
static const int RS_[R_RELS] = {0, 1, 1, 2, 1, 3};   // src type
static const int RD_[R_RELS] = {1, 0, 2, 1, 3, 1};   // dst type

// per-relation dst segmentation (cumulative)
static const int CUMND_[R_RELS + 1] = {0, 200000, 300000, 320000, 520000, 522000, 722000};
#define NDSUM 722000
// per-relation src segmentation (cumulative)
static const int CUMSRC_[R_RELS + 1] = {0, 100000, 300000, 500000, 520000, 720000, 722000};
#define SRCSUM 722000
#define ESUM  4000000

// attention: blocks per relation (32 dst nodes / block)
static const int ABLK_[R_RELS + 1] = {0, 6250, 9375, 10000, 16250, 16313, 22563};
#define ATTN_BLOCKS 22563
// transform: blocks per relation (32 src nodes / block)
static const int TBLK_[R_RELS + 1] = {0, 3125, 9375, 15625, 16250, 22500, 22563};
#define TRANS_BLOCKS 22563

// ---------------- device scratch (static, no allocation) ----------------
__device__ float    g_h[NTOT * HID];
__device__ float    g_K[NTOT * HID];
__device__ float    g_Q[NTOT * HID];
__device__ float    g_V[NTOT * HID];
__device__ __half   g_KVt[(size_t)SRCSUM * 128];  // interleaved fp16: node*128 + h*16 -> [k0..k7, v0..v7]
__device__ float    g_acc[NDSUM * HID];           // per-relation normalized attention output
__device__ unsigned g_cnt[NDSUM];
__device__ int      g_rowptr[NDSUM + 1];
__device__ int      g_cur[NDSUM];
__device__ int      g_bsum[512];
__device__ int      g_srcs[ESUM];

// ---------------- helpers ----------------
__device__ __forceinline__ float gelu_exact(float x) {
    return 0.5f * x * (1.0f + erff(x * 0.70710678118654752f));
}

__device__ __forceinline__ unsigned f2tf(float x) {
    unsigned r;
    asm("cvt.rna.tf32.f32 %0, %1;" : "=r"(r) : "f"(x));
    return r;
}

__device__ __forceinline__ void mma_tf32(float c[4], unsigned a0, unsigned a1,
                                         unsigned a2, unsigned a3,
                                         unsigned b0, unsigned b1) {
    asm volatile(
        "mma.sync.aligned.m16n8k8.row.col.f32.tf32.tf32.f32 "
        "{%0,%1,%2,%3}, {%4,%5,%6,%7}, {%8,%9}, {%0,%1,%2,%3};"
        : "+f"(c[0]), "+f"(c[1]), "+f"(c[2]), "+f"(c[3])
        : "r"(a0), "r"(a1), "r"(a2), "r"(a3), "r"(b0), "r"(b1));
}

__global__ void fill4_u32(uint4* p, unsigned v, int n4) {
    int i = blockIdx.x * blockDim.x + threadIdx.x;
    uint4 val = make_uint4(v, v, v, v);
    for (; i < n4; i += gridDim.x * blockDim.x) p[i] = val;
}

// ---------------- CSR build ----------------
__global__ void count_kernel(const int* __restrict__ dst, unsigned* __restrict__ cnt, int E) {
    int e = blockIdx.x * blockDim.x + threadIdx.x;
    if (e < E) atomicAdd(&cnt[dst[e]], 1u);
}

__global__ void scan1_kernel(const unsigned* __restrict__ cnt, int* __restrict__ row,
                             int* __restrict__ bsum, int n) {
    __shared__ int sm[256];
    int tid = threadIdx.x;
    int base = blockIdx.x * 2048 + tid * 8;
    int vals[8];
    int s = 0;
    #pragma unroll
    for (int i = 0; i < 8; i++) {
        int idx = base + i;
        int t = (idx < n) ? (int)cnt[idx] : 0;
        vals[i] = s;
        s += t;
    }
    sm[tid] = s;
    __syncthreads();
    #pragma unroll
    for (int off = 1; off < 256; off <<= 1) {
        int t = (tid >= off) ? sm[tid - off] : 0;
        __syncthreads();
        sm[tid] += t;
        __syncthreads();
    }
    int excl = sm[tid] - s;
    if (tid == 255) bsum[blockIdx.x] = sm[255];
    #pragma unroll
    for (int i = 0; i < 8; i++) {
        int idx = base + i;
        if (idx < n) row[idx] = excl + vals[i];
    }
}

__global__ void scan2_kernel(int* __restrict__ bsum, int nb) {
    __shared__ int sm[512];
    int tid = threadIdx.x;
    int v = (tid < nb) ? bsum[tid] : 0;
    sm[tid] = v;
    __syncthreads();
    #pragma unroll
    for (int off = 1; off < 512; off <<= 1) {
        int t = (tid >= off) ? sm[tid - off] : 0;
        __syncthreads();
        sm[tid] += t;
        __syncthreads();
    }
    if (tid < nb) bsum[tid] = sm[tid] - v;
}

__global__ void scan3_kernel(int* __restrict__ row, int* __restrict__ cur,
                             const int* __restrict__ bsum, int n, int total) {
    int idx = blockIdx.x * blockDim.x + threadIdx.x;
    if (idx < n) {
        int v = row[idx] + bsum[idx >> 11];
        row[idx] = v;
        cur[idx] = v;
    }
    if (idx == 0) row[n] = total;
}

__global__ void scatter_kernel(const int* __restrict__ src, const int* __restrict__ dst,
                               int* __restrict__ cur, int* __restrict__ srcs, int E) {
    int e = blockIdx.x * blockDim.x + threadIdx.x;
    if (e >= E) return;
    int pos = atomicAdd(&cur[dst[e]], 1);
    srcs[pos] = src[e];
}

// ---------------- tf32 tensor-core GEMM: input projection (relu out) ----------------
// Y[M,64] = relu(X[M,K] @ W[K,64] + B).  Block: 256 threads = 8 warps, 128-row tile.
__global__ void tc_in_kernel(const float* __restrict__ X, const float* __restrict__ W,
                             const float* __restrict__ Bb, float* __restrict__ Y,
                             int M, int K) {
    __shared__ float Xs[128 * 36];
    __shared__ float Ws[32 * 72];
    __shared__ float bs[64];
    int tid = threadIdx.x;
    int w = tid >> 5, lane = tid & 31;
    int g = lane >> 2, q = lane & 3;
    int rowBase = blockIdx.x * 128;
    int wrow = w * 16;
    if (tid < 64) bs[tid] = Bb[tid];
    float C[8][4] = {};
    for (int k0 = 0; k0 < K; k0 += 32) {
        __syncthreads();
        #pragma unroll
        for (int it = 0; it < 16; it++) {
            int idx = tid + it * 256;
            int r = idx >> 5, c = idx & 31;
            int gr = rowBase + r, gc = k0 + c;
            Xs[r * 36 + c] = (gr < M && gc < K) ? X[(size_t)gr * K + gc] : 0.0f;
        }
        #pragma unroll
        for (int it = 0; it < 8; it++) {
            int idx = tid + it * 256;
            int kk = idx >> 6, c = idx & 63;
            int gk = k0 + kk;
            Ws[kk * 72 + c] = (gk < K) ? W[(size_t)gk * 64 + c] : 0.0f;
        }
        __syncthreads();
        #pragma unroll
        for (int ks = 0; ks < 4; ks++) {
            int kb = ks * 8;
            unsigned a0 = f2tf(Xs[(wrow + g) * 36 + kb + q]);
            unsigned a1 = f2tf(Xs[(wrow + g + 8) * 36 + kb + q]);
            unsigned a2 = f2tf(Xs[(wrow + g) * 36 + kb + q + 4]);
            unsigned a3 = f2tf(Xs[(wrow + g + 8) * 36 + kb + q + 4]);
            #pragma unroll
            for (int j = 0; j < 8; j++) {
                unsigned b0 = f2tf(Ws[(kb + q) * 72 + 8 * j + g]);
                unsigned b1 = f2tf(Ws[(kb + q + 4) * 72 + 8 * j + g]);
                mma_tf32(C[j], a0, a1, a2, a3, b0, b1);
            }
        }
    }
    int row0 = rowBase + wrow + g;
    int row1 = row0 + 8;
    #pragma unroll
    for (int j = 0; j < 8; j++) {
        int col = 8 * j + 2 * q;
        if (row0 < M) {
            float2 o = make_float2(fmaxf(C[j][0] + bs[col], 0.0f),
                                   fmaxf(C[j][1] + bs[col + 1], 0.0f));
            *(float2*)(Y + (size_t)row0 * 64 + col) = o;
        }
        if (row1 < M) {
            float2 o = make_float2(fmaxf(C[j][2] + bs[col], 0.0f),
                                   fmaxf(C[j][3] + bs[col + 1], 0.0f));
            *(float2*)(Y + (size_t)row1 * 64 + col) = o;
        }
    }
}

// ---------------- tf32 tensor-core GEMM: fused K/Q/V (K=64, X staged once) ----------------
__global__ void tc_kqv_kernel(const float* __restrict__ X,
                              const float* __restrict__ Wk, const float* __restrict__ Wq,
                              const float* __restrict__ Wv,
                              const float* __restrict__ bk, const float* __restrict__ bq,
                              const float* __restrict__ bv,
                              float* __restrict__ Yk, float* __restrict__ Yq,
                              float* __restrict__ Yv, int M) {
    __shared__ float Xs[128 * 68];
    __shared__ float Ws[32 * 72];
    __shared__ float bs[192];
    int tid = threadIdx.x;
    int w = tid >> 5, lane = tid & 31;
    int g = lane >> 2, q = lane & 3;
    int rowBase = blockIdx.x * 128;
    int wrow = w * 16;
    if (tid < 64) { bs[tid] = bk[tid]; bs[64 + tid] = bq[tid]; bs[128 + tid] = bv[tid]; }
    #pragma unroll
    for (int it = 0; it < 32; it++) {
        int idx = tid + it * 256;
        int r = idx >> 6, c = idx & 63;
        int gr = rowBase + r;
        Xs[r * 68 + c] = (gr < M) ? X[(size_t)gr * 64 + c] : 0.0f;
    }
    const float* Wsel[3] = {Wk, Wq, Wv};
    float* Ysel[3] = {Yk, Yq, Yv};
    int row0 = rowBase + wrow + g;
    int row1 = row0 + 8;
    #pragma unroll
    for (int s = 0; s < 3; s++) {
        float C[8][4] = {};
        #pragma unroll
        for (int kc = 0; kc < 64; kc += 32) {
            __syncthreads();
            #pragma unroll
            for (int it = 0; it < 8; it++) {
                int idx = tid + it * 256;
                int kk = idx >> 6, c = idx & 63;
                Ws[kk * 72 + c] = Wsel[s][(size_t)(kc + kk) * 64 + c];
            }
            __syncthreads();
            #pragma unroll
            for (int ks = 0; ks < 4; ks++) {
                int kb = ks * 8;
                unsigned a0 = f2tf(Xs[(wrow + g) * 68 + kc + kb + q]);
                unsigned a1 = f2tf(Xs[(wrow + g + 8) * 68 + kc + kb + q]);
                unsigned a2 = f2tf(Xs[(wrow + g) * 68 + kc + kb + q + 4]);
                unsigned a3 = f2tf(Xs[(wrow + g + 8) * 68 + kc + kb + q + 4]);
                #pragma unroll
                for (int j = 0; j < 8; j++) {
                    unsigned b0 = f2tf(Ws[(kb + q) * 72 + 8 * j + g]);
                    unsigned b1 = f2tf(Ws[(kb + q + 4) * 72 + 8 * j + g]);
                    mma_tf32(C[j], a0, a1, a2, a3, b0, b1);
                }
            }
        }
        float* Yo = Ysel[s];
        #pragma unroll
        for (int j = 0; j < 8; j++) {
            int col = 8 * j + 2 * q;
            if (row0 < M) {
                float2 o = make_float2(C[j][0] + bs[s * 64 + col],
                                       C[j][1] + bs[s * 64 + col + 1]);
                *(float2*)(Yo + (size_t)row0 * 64 + col) = o;
            }
            if (row1 < M) {
                float2 o = make_float2(C[j][2] + bs[s * 64 + col],
                                       C[j][3] + bs[s * 64 + col + 1]);
                *(float2*)(Yo + (size_t)row1 * 64 + col) = o;
            }
        }
    }
}

// ---------------- tf32 tensor-core adapter: gelu(sum) @ AW + Ab, gated residual ----------------
__global__ void tc_adapter_kernel(const float* __restrict__ a0p, const float* __restrict__ a1p,
                                  const float* __restrict__ a2p,
                                  const float* __restrict__ W, const float* __restrict__ Bb,
                                  const float* __restrict__ skip, int skipIdx,
                                  float* __restrict__ h, int M) {
    __shared__ float Xs[128 * 68];
    __shared__ float Ws[32 * 72];
    __shared__ float bs[64];
    int tid = threadIdx.x;
    int w = tid >> 5, lane = tid & 31;
    int g = lane >> 2, q = lane & 3;
    int rowBase = blockIdx.x * 128;
    int wrow = w * 16;
    if (tid < 64) bs[tid] = Bb[tid];
    #pragma unroll
    for (int it = 0; it < 32; it++) {
        int idx = tid + it * 256;
        int r = idx >> 6, c = idx & 63;
        int node = rowBase + r;
        float v = 0.0f;
        if (node < M) {
            v = a0p[(size_t)node * 64 + c];
            if (a1p) v += a1p[(size_t)node * 64 + c];
            if (a2p) v += a2p[(size_t)node * 64 + c];
        }
        Xs[r * 68 + c] = gelu_exact(v);
    }
    float C[8][4] = {};
    #pragma unroll
    for (int kc = 0; kc < 64; kc += 32) {
        __syncthreads();
        #pragma unroll
        for (int it = 0; it < 8; it++) {
            int idx = tid + it * 256;
            int kk = idx >> 6, c = idx & 63;
            Ws[kk * 72 + c] = W[(size_t)(kc + kk) * 64 + c];
        }
        __syncthreads();
        #pragma unroll
        for (int ks = 0; ks < 4; ks++) {
            int kb = ks * 8;
            unsigned a0 = f2tf(Xs[(wrow + g) * 68 + kc + kb + q]);
            unsigned a1 = f2tf(Xs[(wrow + g + 8) * 68 + kc + kb + q]);
            unsigned a2 = f2tf(Xs[(wrow + g) * 68 + kc + kb + q + 4]);
            unsigned a3 = f2tf(Xs[(wrow + g + 8) * 68 + kc + kb + q + 4]);
            #pragma unroll
            for (int j = 0; j < 8; j++) {
                unsigned b0 = f2tf(Ws[(kb + q) * 72 + 8 * j + g]);
                unsigned b1 = f2tf(Ws[(kb + q + 4) * 72 + 8 * j + g]);
                mma_tf32(C[j], a0, a1, a2, a3, b0, b1);
            }
        }
    }
    float gate = 1.0f / (1.0f + __expf(-skip[skipIdx]));
    float og = 1.0f - gate;
    int row0 = rowBase + wrow + g;
    int row1 = row0 + 8;
    #pragma unroll
    for (int j = 0; j < 8; j++) {
        int col = 8 * j + 2 * q;
        if (row0 < M) {
            float2* hp = (float2*)(h + (size_t)row0 * 64 + col);
            float2 old = *hp;
            *hp = make_float2(gate * (C[j][0] + bs[col])     + og * old.x,
                              gate * (C[j][1] + bs[col + 1]) + og * old.y);
        }
        if (row1 < M) {
            float2* hp = (float2*)(h + (size_t)row1 * 64 + col);
            float2 old = *hp;
            *hp = make_float2(gate * (C[j][2] + bs[col])     + og * old.x,
                              gate * (C[j][3] + bs[col + 1]) + og * old.y);
        }
    }
}

// ---------------- per-relation K/V transform -> interleaved fp16 ----------------
struct TransRel {
    const float *K, *V, *A, *Mm, *P;
    __half* KVt;
    int Nsrc;
};
struct TransCtx {
    TransRel rel[R_RELS];
    int blkOff[R_RELS + 1];
};

__global__ void transform_kernel(TransCtx p) {
    __shared__ float As[512];   // [d*64 + f*8 + h]
    __shared__ float Ms[512];
    __shared__ float Ps[8];
    int b = blockIdx.x;
    int r = 0;
    #pragma unroll
    for (int i = 1; i < R_RELS; i++) if (b >= p.blkOff[i]) r = i;
    const TransRel rc = p.rel[r];
    int tid = threadIdx.x;
    #pragma unroll
    for (int it = 0; it < 2; it++) {
        int i = tid + it * 256;
        int h = i >> 6, d = (i >> 3) & 7, f = i & 7;
        As[d * 64 + f * 8 + h] = rc.A[i];
        Ms[d * 64 + f * 8 + h] = rc.Mm[i];
    }
    if (tid < 8) Ps[tid] = rc.P[tid];
    __syncthreads();

    int node = (b - p.blkOff[r]) * 32 + (tid >> 3);
    int h = tid & 7;
    if (node >= rc.Nsrc) return;

    const float4* kp = (const float4*)(rc.K + (size_t)node * 64 + h * 8);
    float4 k0 = kp[0], k1 = kp[1];
    float k[8] = {k0.x, k0.y, k0.z, k0.w, k1.x, k1.y, k1.z, k1.w};
    const float4* vp = (const float4*)(rc.V + (size_t)node * 64 + h * 8);
    float4 v0 = vp[0], v1 = vp[1];
    float v[8] = {v0.x, v0.y, v0.z, v0.w, v1.x, v1.y, v1.z, v1.w};

    float ps = Ps[h] * 0.35355339059327373f;
    float kt[8], vt[8];
    #pragma unroll
    for (int f = 0; f < 8; f++) {
        float ka = 0.0f, va = 0.0f;
        #pragma unroll
        for (int d = 0; d < 8; d++) {
            ka += k[d] * As[d * 64 + f * 8 + h];
            va += v[d] * Ms[d * 64 + f * 8 + h];
        }
        kt[f] = ka * ps;
        vt[f] = va;
    }
    __half2 pk[4], pv[4];
    #pragma unroll
    for (int i = 0; i < 4; i++) {
        pk[i] = __float22half2_rn(make_float2(kt[2 * i], kt[2 * i + 1]));
        pv[i] = __float22half2_rn(make_float2(vt[2 * i], vt[2 * i + 1]));
    }
    uint4* out = (uint4*)(rc.KVt + (size_t)node * 128 + h * 16);
    out[0] = *(uint4*)pk;
    out[1] = *(uint4*)pv;
}

// ---------------- dst-centric online-softmax attention (fp16 gather) ----------------
struct AttnRel {
    const __half* KVt;
    const float* Q;
    const int* rowPtr;
    float* acc;
    int Nd;
};
struct AttnCtx {
    AttnRel rel[R_RELS];
    int blkOff[R_RELS + 1];
};

__global__ void attn_kernel(AttnCtx p, const int* __restrict__ srcs) {
    int b = blockIdx.x;
    int r = 0;
    #pragma unroll
    for (int i = 1; i < R_RELS; i++) if (b >= p.blkOff[i]) r = i;
    const AttnRel rc = p.rel[r];
    int tid = threadIdx.x;

    int node = (b - p.blkOff[r]) * 32 + (tid >> 3);
    int h = tid & 7;
    if (node >= rc.Nd) return;

    const float4* qp = (const float4*)(rc.Q + (size_t)node * 64 + h * 8);
    float4 q0 = qp[0], q1 = qp[1];
    float q[8] = {q0.x, q0.y, q0.z, q0.w, q1.x, q1.y, q1.z, q1.w};

    int beg = rc.rowPtr[node];
    int end = rc.rowPtr[node + 1];

    float m = -INFINITY, den = 0.0f;
    float a[8] = {};

    #pragma unroll 2
    for (int j = beg; j < end; j++) {
        int s = __ldg(&srcs[j]);
        const uint4* kvp = (const uint4*)(rc.KVt + (size_t)s * 128 + h * 16);
        uint4 kw = kvp[0];
        uint4 vw = kvp[1];
        const __half2* kh = (const __half2*)&kw;
        const __half2* vh = (const __half2*)&vw;
        float2 kf0 = __half22float2(kh[0]), kf1 = __half22float2(kh[1]);
        float2 kf2 = __half22float2(kh[2]), kf3 = __half22float2(kh[3]);
        float2 vf0 = __half22float2(vh[0]), vf1 = __half22float2(vh[1]);
        float2 vf2 = __half22float2(vh[2]), vf3 = __half22float2(vh[3]);

        float sc = q[0] * kf0.x + q[1] * kf0.y + q[2] * kf1.x + q[3] * kf1.y
                 + q[4] * kf2.x + q[5] * kf2.y + q[6] * kf3.x + q[7] * kf3.y;

        float mn = fmaxf(m, sc);
        float cOld = __expf(m - mn);
        float ex = __expf(sc - mn);
        den = den * cOld + ex;
        a[0] = a[0] * cOld + ex * vf0.x;
        a[1] = a[1] * cOld + ex * vf0.y;
        a[2] = a[2] * cOld + ex * vf1.x;
        a[3] = a[3] * cOld + ex * vf1.y;
        a[4] = a[4] * cOld + ex * vf2.x;
        a[5] = a[5] * cOld + ex * vf2.y;
        a[6] = a[6] * cOld + ex * vf3.x;
        a[7] = a[7] * cOld + ex * vf3.y;
        m = mn;
    }

    float inv = (den > 0.0f) ? 1.0f / den : 0.0f;
    float4* op = (float4*)(rc.acc + (size_t)node * 64 + h * 8);
    op[0] = make_float4(a[0] * inv, a[1] * inv, a[2] * inv, a[3] * inv);
    op[1] = make_float4(a[4] * inv, a[5] * inv, a[6] * inv, a[7] * inv);
}

// ---------------- final head ----------------
__global__ void out_kernel(const float* __restrict__ h, const float* __restrict__ Wo,
                           const float* __restrict__ bo, float* __restrict__ y, int n) {
    __shared__ float ws[256];
    __shared__ float bs[4];
    if (threadIdx.x < 256) ws[threadIdx.x] = Wo[threadIdx.x];
    if (threadIdx.x < 4) bs[threadIdx.x] = bo[threadIdx.x];
    __syncthreads();
    int node = blockIdx.x * blockDim.x + threadIdx.x;
    if (node >= n) return;
    const float4* hp = (const float4*)(h + (size_t)node * 64);
    float a0 = bs[0], a1 = bs[1], a2 = bs[2], a3 = bs[3];
    #pragma unroll
    for (int i = 0; i < 16; i++) {
        float4 hv = hp[i];
        const float* w = ws + 16 * i;
        a0 += hv.x * w[0]  + hv.y * w[4]  + hv.z * w[8]  + hv.w * w[12];
        a1 += hv.x * w[1]  + hv.y * w[5]  + hv.z * w[9]  + hv.w * w[13];
        a2 += hv.x * w[2]  + hv.y * w[6]  + hv.z * w[10] + hv.w * w[14];
        a3 += hv.x * w[3]  + hv.y * w[7]  + hv.z * w[11] + hv.w * w[15];
    }
    ((float4*)y)[node] = make_float4(a0, a1, a2, a3);
}

// ---------------- host launcher ----------------
static inline int cdiv(int a, int b) { return (a + b - 1) / b; }

extern "C" void kernel_launch(void* const* d_in, const int* in_sizes, int n_in,
                              void* d_out, int out_size) {
    (void)n_in; (void)out_size;

    const float* x[T_TYPES]   = {(const float*)d_in[0], (const float*)d_in[1],
                                 (const float*)d_in[2], (const float*)d_in[3]};
    const float* Win[T_TYPES] = {(const float*)d_in[4], (const float*)d_in[6],
                                 (const float*)d_in[8], (const float*)d_in[10]};
    const float* bin[T_TYPES] = {(const float*)d_in[5], (const float*)d_in[7],
                                 (const float*)d_in[9], (const float*)d_in[11]};

    const float *KW, *Kb, *QW, *Qb, *VW, *Vb, *AW, *Ab;
    if (in_sizes[13] > 4096) {
        KW = (const float*)d_in[12]; QW = (const float*)d_in[13];
        VW = (const float*)d_in[14]; AW = (const float*)d_in[15];
        Kb = (const float*)d_in[16]; Qb = (const float*)d_in[17];
        Vb = (const float*)d_in[18]; Ab = (const float*)d_in[19];
    } else {
        KW = (const float*)d_in[12]; Kb = (const float*)d_in[13];
        QW = (const float*)d_in[14]; Qb = (const float*)d_in[15];
        VW = (const float*)d_in[16]; Vb = (const float*)d_in[17];
        AW = (const float*)d_in[18]; Ab = (const float*)d_in[19];
    }
    const float* skip  = (const float*)d_in[20];
    const float* A_rel = (const float*)d_in[21];
    const float* M_rel = (const float*)d_in[22];
    const float* P_rel = (const float*)d_in[23];
    const float* W_out = (const float*)d_in[24];
    const float* b_out = (const float*)d_in[25];
    const int* ei[R_RELS] = {(const int*)d_in[26], (const int*)d_in[27], (const int*)d_in[28],
                             (const int*)d_in[29], (const int*)d_in[30], (const int*)d_in[31]};

    float *hB, *kB, *qB, *vB, *accB;
    __half* kvtB;
    unsigned* cntB;
    int *rowB, *curB, *bsumB, *srcsB;
    cudaGetSymbolAddress((void**)&hB,   g_h);
    cudaGetSymbolAddress((void**)&kB,   g_K);
    cudaGetSymbolAddress((void**)&qB,   g_Q);
    cudaGetSymbolAddress((void**)&vB,   g_V);
    cudaGetSymbolAddress((void**)&kvtB, g_KVt);
    cudaGetSymbolAddress((void**)&accB, g_acc);
    cudaGetSymbolAddress((void**)&cntB, g_cnt);
    cudaGetSymbolAddress((void**)&rowB, g_rowptr);
    cudaGetSymbolAddress((void**)&curB, g_cur);
    cudaGetSymbolAddress((void**)&bsumB, g_bsum);
    cudaGetSymbolAddress((void**)&srcsB, g_srcs);

    // ---- CSR build (once; edge lists constant across layers) ----
    fill4_u32<<<1024, 256>>>((uint4*)cntB, 0u, NDSUM / 4);
    for (int r = 0; r < R_RELS; r++) {
        count_kernel<<<cdiv(E_[r], 256), 256>>>(ei[r] + E_[r], cntB + CUMND_[r], E_[r]);
    }
    int nScanBlocks = cdiv(NDSUM, 2048);
    scan1_kernel<<<nScanBlocks, 256>>>(cntB, rowB, bsumB, NDSUM);
    scan2_kernel<<<1, 512>>>(bsumB, nScanBlocks);
    scan3_kernel<<<cdiv(NDSUM, 256), 256>>>(rowB, curB, bsumB, NDSUM, ESUM);
    for (int r = 0; r < R_RELS; r++) {
        scatter_kernel<<<cdiv(E_[r], 256), 256>>>(ei[r], ei[r] + E_[r],
                                                  curB + CUMND_[r], srcsB, E_[r]);
    }

    // ---- input projections (tensor cores) ----
    for (int t = 0; t < T_TYPES; t++) {
        tc_in_kernel<<<cdiv(N_[t], 128), 256>>>(
            x[t], Win[t], bin[t], hB + (size_t)OFF_[t] * HID, N_[t], F_[t]);
    }

    for (int l = 0; l < LAYERS; l++) {
        // fused K/Q/V projections per type (tensor cores)
        for (int t = 0; t < T_TYPES; t++) {
            int base = l * T_TYPES + t;
            tc_kqv_kernel<<<cdiv(N_[t], 128), 256>>>(
                hB + (size_t)OFF_[t] * HID,
                KW + (size_t)base * 4096, QW + (size_t)base * 4096, VW + (size_t)base * 4096,
                Kb + (size_t)base * 64,   Qb + (size_t)base * 64,   Vb + (size_t)base * 64,
                kB + (size_t)OFF_[t] * HID, qB + (size_t)OFF_[t] * HID, vB + (size_t)OFF_[t] * HID,
                N_[t]);
        }

        // per-relation K/V transform -> interleaved fp16
        TransCtx tp;
        for (int r = 0; r < R_RELS; r++) {
            int s = RS_[r];
            int relBase = l * R_RELS + r;
            tp.rel[r].K  = kB + (size_t)OFF_[s] * HID;
            tp.rel[r].V  = vB + (size_t)OFF_[s] * HID;
            tp.rel[r].A  = A_rel + (size_t)relBase * 512;
            tp.rel[r].Mm = M_rel + (size_t)relBase * 512;
            tp.rel[r].P  = P_rel + (size_t)relBase * 8;
            tp.rel[r].KVt = kvtB + (size_t)CUMSRC_[r] * 128;
            tp.rel[r].Nsrc = N_[s];
        }
        for (int i = 0; i <= R_RELS; i++) tp.blkOff[i] = TBLK_[i];
        transform_kernel<<<TRANS_BLOCKS, 256>>>(tp);

        // attention over all relations, one launch
        AttnCtx p;
        for (int r = 0; r < R_RELS; r++) {
            int d = RD_[r];
            p.rel[r].KVt = kvtB + (size_t)CUMSRC_[r] * 128;
            p.rel[r].Q   = qB + (size_t)OFF_[d] * HID;
            p.rel[r].rowPtr = rowB + CUMND_[r];
            p.rel[r].acc = accB + (size_t)CUMND_[r] * HID;
            p.rel[r].Nd = N_[d];
        }
        for (int i = 0; i <= R_RELS; i++) p.blkOff[i] = ABLK_[i];
        attn_kernel<<<ATTN_BLOCKS, 256>>>(p, srcsB);

        // fused adapter per type (tensor cores); dst rels: author<-{1}, paper<-{0,3,5}, term<-{2}, conf<-{4}
        static const int relsByType[T_TYPES][3] = {{1, -1, -1}, {0, 3, 5}, {2, -1, -1}, {4, -1, -1}};
        for (int t = 0; t < T_TYPES; t++) {
            int base = l * T_TYPES + t;
            const float *a0 = accB + (size_t)CUMND_[relsByType[t][0]] * HID;
            const float *a1 = (relsByType[t][1] >= 0) ? accB + (size_t)CUMND_[relsByType[t][1]] * HID : nullptr;
            const float *a2 = (relsByType[t][2] >= 0) ? accB + (size_t)CUMND_[relsByType[t][2]] * HID : nullptr;
            tc_adapter_kernel<<<cdiv(N_[t], 128), 256>>>(
                a0, a1, a2,
                AW + (size_t)base * 4096, Ab + (size_t)base * 64,
                skip, base,
                hB + (size_t)OFF_[t] * HID, N_[t]);
        }
    }

    // final head on author nodes
    out_kernel<<<cdiv(N_[0], 256), 256>>>(hB, W_out, b_out, (float*)d_out, N_[0]);
}

// round 9
// speedup vs baseline: 1.4999x; 1.0394x over previous
#include <cuda_runtime.h>
#include <cuda_fp16.h>
#include <math.h>

// ---------------- problem constants ----------------
#define T_TYPES 4
#define R_RELS 6
#define HID 64
#define HEADS 8
#define DH 8
#define LAYERS 2
#define OUT_DIM 4

static const int N_[T_TYPES]   = {100000, 200000, 20000, 2000};
static const int F_[T_TYPES]   = {334, 512, 128, 128};
static const int OFF_[T_TYPES] = {0, 100000, 300000, 320000};
#define NTOT 322000
static const int E_[R_RELS]  = {800000, 800000, 1000000, 1000000, 200000, 200000};
static const int RS_[R_RELS] = {0, 1, 1, 2, 1, 3};   // src type
static const int RD_[R_RELS] = {1, 0, 2, 1, 3, 1};   // dst type

// per-relation dst segmentation (cumulative)
static const int CUMND_[R_RELS + 1] = {0, 200000, 300000, 320000, 520000, 522000, 722000};
#define NDSUM 722000
// per-relation src segmentation (cumulative)
static const int CUMSRC_[R_RELS + 1] = {0, 100000, 300000, 500000, 520000, 720000, 722000};
#define SRCSUM 722000
#define ESUM  4000000

// attention: blocks per relation (32 dst nodes / block)
static const int ABLK_[R_RELS + 1] = {0, 6250, 9375, 10000, 16250, 16313, 22563};
#define ATTN_BLOCKS 22563

// ---------------- device scratch (static, no allocation) ----------------
__device__ float    g_h[NTOT * HID];
__device__ float    g_Q[NTOT * HID];
__device__ __half   g_KVt[(size_t)SRCSUM * 128];  // interleaved fp16: node*128 + h*16 -> [k0..k7, v0..v7]
__device__ float    g_acc[NDSUM * HID];           // per-relation normalized attention output
__device__ float    g_Wkt[LAYERS * R_RELS * 4096];  // folded K weights (A_rel, P, scale folded in)
__device__ float    g_Wvt[LAYERS * R_RELS * 4096];  // folded V weights (M_rel folded in)
__device__ float    g_bkt[LAYERS * R_RELS * 64];
__device__ float    g_bvt[LAYERS * R_RELS * 64];
__device__ unsigned g_cnt[NDSUM];
__device__ int      g_rowptr[NDSUM + 1];
__device__ int      g_cur[NDSUM];
__device__ int      g_bsum[512];
__device__ int      g_srcs[ESUM];

// ---------------- helpers ----------------
__device__ __forceinline__ float gelu_exact(float x) {
    return 0.5f * x * (1.0f + erff(x * 0.70710678118654752f));
}

__device__ __forceinline__ unsigned f2tf(float x) {
    unsigned r;
    asm("cvt.rna.tf32.f32 %0, %1;" : "=r"(r) : "f"(x));
    return r;
}

__device__ __forceinline__ void mma_tf32(float c[4], unsigned a0, unsigned a1,
                                         unsigned a2, unsigned a3,
                                         unsigned b0, unsigned b1) {
    asm volatile(
        "mma.sync.aligned.m16n8k8.row.col.f32.tf32.tf32.f32 "
        "{%0,%1,%2,%3}, {%4,%5,%6,%7}, {%8,%9}, {%0,%1,%2,%3};"
        : "+f"(c[0]), "+f"(c[1]), "+f"(c[2]), "+f"(c[3])
        : "r"(a0), "r"(a1), "r"(a2), "r"(a3), "r"(b0), "r"(b1));
}

__global__ void fill4_u32(uint4* p, unsigned v, int n4) {
    int i = blockIdx.x * blockDim.x + threadIdx.x;
    uint4 val = make_uint4(v, v, v, v);
    for (; i < n4; i += gridDim.x * blockDim.x) p[i] = val;
}

// ---------------- CSR build ----------------
__global__ void count_kernel(const int* __restrict__ dst, unsigned* __restrict__ cnt, int E) {
    int e = blockIdx.x * blockDim.x + threadIdx.x;
    if (e < E) atomicAdd(&cnt[dst[e]], 1u);
}

__global__ void scan1_kernel(const unsigned* __restrict__ cnt, int* __restrict__ row,
                             int* __restrict__ bsum, int n) {
    __shared__ int sm[256];
    int tid = threadIdx.x;
    int base = blockIdx.x * 2048 + tid * 8;
    int vals[8];
    int s = 0;
    #pragma unroll
    for (int i = 0; i < 8; i++) {
        int idx = base + i;
        int t = (idx < n) ? (int)cnt[idx] : 0;
        vals[i] = s;
        s += t;
    }
    sm[tid] = s;
    __syncthreads();
    #pragma unroll
    for (int off = 1; off < 256; off <<= 1) {
        int t = (tid >= off) ? sm[tid - off] : 0;
        __syncthreads();
        sm[tid] += t;
        __syncthreads();
    }
    int excl = sm[tid] - s;
    if (tid == 255) bsum[blockIdx.x] = sm[255];
    #pragma unroll
    for (int i = 0; i < 8; i++) {
        int idx = base + i;
        if (idx < n) row[idx] = excl + vals[i];
    }
}

__global__ void scan2_kernel(int* __restrict__ bsum, int nb) {
    __shared__ int sm[512];
    int tid = threadIdx.x;
    int v = (tid < nb) ? bsum[tid] : 0;
    sm[tid] = v;
    __syncthreads();
    #pragma unroll
    for (int off = 1; off < 512; off <<= 1) {
        int t = (tid >= off) ? sm[tid - off] : 0;
        __syncthreads();
        sm[tid] += t;
        __syncthreads();
    }
    if (tid < nb) bsum[tid] = sm[tid] - v;
}

__global__ void scan3_kernel(int* __restrict__ row, int* __restrict__ cur,
                             const int* __restrict__ bsum, int n, int total) {
    int idx = blockIdx.x * blockDim.x + threadIdx.x;
    if (idx < n) {
        int v = row[idx] + bsum[idx >> 11];
        row[idx] = v;
        cur[idx] = v;
    }
    if (idx == 0) row[n] = total;
}

__global__ void scatter_kernel(const int* __restrict__ src, const int* __restrict__ dst,
                               int* __restrict__ cur, int* __restrict__ srcs, int E) {
    int e = blockIdx.x * blockDim.x + threadIdx.x;
    if (e >= E) return;
    int pos = atomicAdd(&cur[dst[e]], 1);
    srcs[pos] = src[e];
}

// ---------------- weight folding: W~k = KW @ blockdiag(A)·P·scale, W~v = VW @ blockdiag(M) ----------------
__global__ void fold_kernel(const float* __restrict__ KW, const float* __restrict__ Kb,
                            const float* __restrict__ VW, const float* __restrict__ Vb,
                            const float* __restrict__ A_rel, const float* __restrict__ M_rel,
                            const float* __restrict__ P_rel,
                            float* __restrict__ Wkt, float* __restrict__ Wvt,
                            float* __restrict__ bkt, float* __restrict__ bvt) {
    const int RSL[R_RELS] = {0, 1, 1, 2, 1, 3};
    int lr = blockIdx.x;                  // 0 .. LAYERS*R_RELS-1
    int l = lr / R_RELS, r = lr % R_RELS;
    int base = l * T_TYPES + RSL[r];
    __shared__ float As[512], Ms[512], Ps[8];
    int tid = threadIdx.x;
    #pragma unroll
    for (int it = 0; it < 2; it++) {
        int i = tid + it * 256;
        As[i] = A_rel[(size_t)lr * 512 + i];   // [h][d][f]
        Ms[i] = M_rel[(size_t)lr * 512 + i];
    }
    if (tid < 8) Ps[tid] = P_rel[lr * 8 + tid] * 0.35355339059327373f;
    __syncthreads();
    for (int o = tid; o < 4096; o += 256) {
        int i = o >> 6, c = o & 63;
        int h = c >> 3, f = c & 7;
        float sk = 0.0f, sv = 0.0f;
        #pragma unroll
        for (int d = 0; d < 8; d++) {
            sk += KW[(size_t)base * 4096 + i * 64 + h * 8 + d] * As[h * 64 + d * 8 + f];
            sv += VW[(size_t)base * 4096 + i * 64 + h * 8 + d] * Ms[h * 64 + d * 8 + f];
        }
        Wkt[(size_t)lr * 4096 + o] = sk * Ps[h];
        Wvt[(size_t)lr * 4096 + o] = sv;
    }
    if (tid < 64) {
        int h = tid >> 3, f = tid & 7;
        float sk = 0.0f, sv = 0.0f;
        #pragma unroll
        for (int d = 0; d < 8; d++) {
            sk += Kb[base * 64 + h * 8 + d] * As[h * 64 + d * 8 + f];
            sv += Vb[base * 64 + h * 8 + d] * Ms[h * 64 + d * 8 + f];
        }
        bkt[lr * 64 + tid] = sk * Ps[h];
        bvt[lr * 64 + tid] = sv;
    }
}

// ---------------- tf32 tensor-core GEMM: input projection (relu out) ----------------
__global__ void tc_in_kernel(const float* __restrict__ X, const float* __restrict__ W,
                             const float* __restrict__ Bb, float* __restrict__ Y,
                             int M, int K) {
    __shared__ float Xs[128 * 36];
    __shared__ float Ws[32 * 72];
    __shared__ float bs[64];
    int tid = threadIdx.x;
    int w = tid >> 5, lane = tid & 31;
    int g = lane >> 2, q = lane & 3;
    int rowBase = blockIdx.x * 128;
    int wrow = w * 16;
    if (tid < 64) bs[tid] = Bb[tid];
    float C[8][4] = {};
    for (int k0 = 0; k0 < K; k0 += 32) {
        __syncthreads();
        #pragma unroll
        for (int it = 0; it < 16; it++) {
            int idx = tid + it * 256;
            int r = idx >> 5, c = idx & 31;
            int gr = rowBase + r, gc = k0 + c;
            Xs[r * 36 + c] = (gr < M && gc < K) ? X[(size_t)gr * K + gc] : 0.0f;
        }
        #pragma unroll
        for (int it = 0; it < 8; it++) {
            int idx = tid + it * 256;
            int kk = idx >> 6, c = idx & 63;
            int gk = k0 + kk;
            Ws[kk * 72 + c] = (gk < K) ? W[(size_t)gk * 64 + c] : 0.0f;
        }
        __syncthreads();
        #pragma unroll
        for (int ks = 0; ks < 4; ks++) {
            int kb = ks * 8;
            unsigned a0 = f2tf(Xs[(wrow + g) * 36 + kb + q]);
            unsigned a1 = f2tf(Xs[(wrow + g + 8) * 36 + kb + q]);
            unsigned a2 = f2tf(Xs[(wrow + g) * 36 + kb + q + 4]);
            unsigned a3 = f2tf(Xs[(wrow + g + 8) * 36 + kb + q + 4]);
            #pragma unroll
            for (int j = 0; j < 8; j++) {
                unsigned b0 = f2tf(Ws[(kb + q) * 72 + 8 * j + g]);
                unsigned b1 = f2tf(Ws[(kb + q + 4) * 72 + 8 * j + g]);
                mma_tf32(C[j], a0, a1, a2, a3, b0, b1);
            }
        }
    }
    int row0 = rowBase + wrow + g;
    int row1 = row0 + 8;
    #pragma unroll
    for (int j = 0; j < 8; j++) {
        int col = 8 * j + 2 * q;
        if (row0 < M) {
            float2 o = make_float2(fmaxf(C[j][0] + bs[col], 0.0f),
                                   fmaxf(C[j][1] + bs[col + 1], 0.0f));
            *(float2*)(Y + (size_t)row0 * 64 + col) = o;
        }
        if (row1 < M) {
            float2 o = make_float2(fmaxf(C[j][2] + bs[col], 0.0f),
                                   fmaxf(C[j][3] + bs[col + 1], 0.0f));
            *(float2*)(Y + (size_t)row1 * 64 + col) = o;
        }
    }
}

// ---------------- tf32 multi-output GEMM: Q (fp32) + per-relation K~/V~ (fp16 interleaved) ----------------
struct KqvtPass {
    const float* W;     // [64,64] weights
    const float* b;     // [64] bias
    float* outF;        // fp32 output (Q) or null
    __half* outH;       // fp16 interleaved KVt base or null
    int kvSel;          // 0 = K half, 1 = V half
};
struct KqvtCtx {
    KqvtPass pass[7];
    int nPass;
};

__global__ void tc_kqvt_kernel(const float* __restrict__ X, KqvtCtx ctx, int M) {
    __shared__ float Xs[128 * 68];
    __shared__ float Ws[32 * 72];
    int tid = threadIdx.x;
    int w = tid >> 5, lane = tid & 31;
    int g = lane >> 2, q = lane & 3;
    int rowBase = blockIdx.x * 128;
    int wrow = w * 16;
    #pragma unroll
    for (int it = 0; it < 32; it++) {
        int idx = tid + it * 256;
        int r = idx >> 6, c = idx & 63;
        int gr = rowBase + r;
        Xs[r * 68 + c] = (gr < M) ? X[(size_t)gr * 64 + c] : 0.0f;
    }
    int row0 = rowBase + wrow + g;
    int row1 = row0 + 8;
    for (int s = 0; s < ctx.nPass; s++) {
        const KqvtPass P = ctx.pass[s];
        float C[8][4] = {};
        #pragma unroll
        for (int kc = 0; kc < 64; kc += 32) {
            __syncthreads();
            #pragma unroll
            for (int it = 0; it < 8; it++) {
                int idx = tid + it * 256;
                int kk = idx >> 6, c = idx & 63;
                Ws[kk * 72 + c] = P.W[(size_t)(kc + kk) * 64 + c];
            }
            __syncthreads();
            #pragma unroll
            for (int ks = 0; ks < 4; ks++) {
                int kb = ks * 8;
                unsigned a0 = f2tf(Xs[(wrow + g) * 68 + kc + kb + q]);
                unsigned a1 = f2tf(Xs[(wrow + g + 8) * 68 + kc + kb + q]);
                unsigned a2 = f2tf(Xs[(wrow + g) * 68 + kc + kb + q + 4]);
                unsigned a3 = f2tf(Xs[(wrow + g + 8) * 68 + kc + kb + q + 4]);
                #pragma unroll
                for (int j = 0; j < 8; j++) {
                    unsigned b0 = f2tf(Ws[(kb + q) * 72 + 8 * j + g]);
                    unsigned b1 = f2tf(Ws[(kb + q + 4) * 72 + 8 * j + g]);
                    mma_tf32(C[j], a0, a1, a2, a3, b0, b1);
                }
            }
        }
        if (P.outF) {
            #pragma unroll
            for (int j = 0; j < 8; j++) {
                int col = 8 * j + 2 * q;
                float b0 = __ldg(&P.b[col]), b1 = __ldg(&P.b[col + 1]);
                if (row0 < M)
                    *(float2*)(P.outF + (size_t)row0 * 64 + col) =
                        make_float2(C[j][0] + b0, C[j][1] + b1);
                if (row1 < M)
                    *(float2*)(P.outF + (size_t)row1 * 64 + col) =
                        make_float2(C[j][2] + b0, C[j][3] + b1);
            }
        } else {
            // head j occupies cols [8j, 8j+8); this thread holds local cols 2q, 2q+1
            #pragma unroll
            for (int j = 0; j < 8; j++) {
                int col = 8 * j + 2 * q;
                float b0 = __ldg(&P.b[col]), b1 = __ldg(&P.b[col + 1]);
                if (row0 < M) {
                    __half2 o = __float22half2_rn(make_float2(C[j][0] + b0, C[j][1] + b1));
                    *(__half2*)(P.outH + (size_t)row0 * 128 + j * 16 + P.kvSel * 8 + 2 * q) = o;
                }
                if (row1 < M) {
                    __half2 o = __float22half2_rn(make_float2(C[j][2] + b0, C[j][3] + b1));
                    *(__half2*)(P.outH + (size_t)row1 * 128 + j * 16 + P.kvSel * 8 + 2 * q) = o;
                }
            }
        }
    }
}

// ---------------- tf32 tensor-core adapter: gelu(sum) @ AW + Ab, gated residual ----------------
__global__ void tc_adapter_kernel(const float* __restrict__ a0p, const float* __restrict__ a1p,
                                  const float* __restrict__ a2p,
                                  const float* __restrict__ W, const float* __restrict__ Bb,
                                  const float* __restrict__ skip, int skipIdx,
                                  float* __restrict__ h, int M) {
    __shared__ float Xs[128 * 68];
    __shared__ float Ws[32 * 72];
    __shared__ float bs[64];
    int tid = threadIdx.x;
    int w = tid >> 5, lane = tid & 31;
    int g = lane >> 2, q = lane & 3;
    int rowBase = blockIdx.x * 128;
    int wrow = w * 16;
    if (tid < 64) bs[tid] = Bb[tid];
    #pragma unroll
    for (int it = 0; it < 32; it++) {
        int idx = tid + it * 256;
        int r = idx >> 6, c = idx & 63;
        int node = rowBase + r;
        float v = 0.0f;
        if (node < M) {
            v = a0p[(size_t)node * 64 + c];
            if (a1p) v += a1p[(size_t)node * 64 + c];
            if (a2p) v += a2p[(size_t)node * 64 + c];
        }
        Xs[r * 68 + c] = gelu_exact(v);
    }
    float C[8][4] = {};
    #pragma unroll
    for (int kc = 0; kc < 64; kc += 32) {
        __syncthreads();
        #pragma unroll
        for (int it = 0; it < 8; it++) {
            int idx = tid + it * 256;
            int kk = idx >> 6, c = idx & 63;
            Ws[kk * 72 + c] = W[(size_t)(kc + kk) * 64 + c];
        }
        __syncthreads();
        #pragma unroll
        for (int ks = 0; ks < 4; ks++) {
            int kb = ks * 8;
            unsigned a0 = f2tf(Xs[(wrow + g) * 68 + kc + kb + q]);
            unsigned a1 = f2tf(Xs[(wrow + g + 8) * 68 + kc + kb + q]);
            unsigned a2 = f2tf(Xs[(wrow + g) * 68 + kc + kb + q + 4]);
            unsigned a3 = f2tf(Xs[(wrow + g + 8) * 68 + kc + kb + q + 4]);
            #pragma unroll
            for (int j = 0; j < 8; j++) {
                unsigned b0 = f2tf(Ws[(kb + q) * 72 + 8 * j + g]);
                unsigned b1 = f2tf(Ws[(kb + q + 4) * 72 + 8 * j + g]);
                mma_tf32(C[j], a0, a1, a2, a3, b0, b1);
            }
        }
    }
    float gate = 1.0f / (1.0f + __expf(-skip[skipIdx]));
    float og = 1.0f - gate;
    int row0 = rowBase + wrow + g;
    int row1 = row0 + 8;
    #pragma unroll
    for (int j = 0; j < 8; j++) {
        int col = 8 * j + 2 * q;
        if (row0 < M) {
            float2* hp = (float2*)(h + (size_t)row0 * 64 + col);
            float2 old = *hp;
            *hp = make_float2(gate * (C[j][0] + bs[col])     + og * old.x,
                              gate * (C[j][1] + bs[col + 1]) + og * old.y);
        }
        if (row1 < M) {
            float2* hp = (float2*)(h + (size_t)row1 * 64 + col);
            float2 old = *hp;
            *hp = make_float2(gate * (C[j][2] + bs[col])     + og * old.x,
                              gate * (C[j][3] + bs[col + 1]) + og * old.y);
        }
    }
}

// ---------------- dst-centric online-softmax attention (fp16 gather) ----------------
struct AttnRel {
    const __half* KVt;
    const float* Q;
    const int* rowPtr;
    float* acc;
    int Nd;
};
struct AttnCtx {
    AttnRel rel[R_RELS];
    int blkOff[R_RELS + 1];
};

__global__ void attn_kernel(AttnCtx p, const int* __restrict__ srcs) {
    int b = blockIdx.x;
    int r = 0;
    #pragma unroll
    for (int i = 1; i < R_RELS; i++) if (b >= p.blkOff[i]) r = i;
    const AttnRel rc = p.rel[r];
    int tid = threadIdx.x;

    int node = (b - p.blkOff[r]) * 32 + (tid >> 3);
    int h = tid & 7;
    if (node >= rc.Nd) return;

    const float4* qp = (const float4*)(rc.Q + (size_t)node * 64 + h * 8);
    float4 q0 = qp[0], q1 = qp[1];
    float q[8] = {q0.x, q0.y, q0.z, q0.w, q1.x, q1.y, q1.z, q1.w};

    int beg = rc.rowPtr[node];
    int end = rc.rowPtr[node + 1];

    float m = -INFINITY, den = 0.0f;
    float a[8] = {};

    #pragma unroll 2
    for (int j = beg; j < end; j++) {
        int s = __ldg(&srcs[j]);
        const uint4* kvp = (const uint4*)(rc.KVt + (size_t)s * 128 + h * 16);
        uint4 kw = kvp[0];
        uint4 vw = kvp[1];
        const __half2* kh = (const __half2*)&kw;
        const __half2* vh = (const __half2*)&vw;
        float2 kf0 = __half22float2(kh[0]), kf1 = __half22float2(kh[1]);
        float2 kf2 = __half22float2(kh[2]), kf3 = __half22float2(kh[3]);
        float2 vf0 = __half22float2(vh[0]), vf1 = __half22float2(vh[1]);
        float2 vf2 = __half22float2(vh[2]), vf3 = __half22float2(vh[3]);

        float sc = q[0] * kf0.x + q[1] * kf0.y + q[2] * kf1.x + q[3] * kf1.y
                 + q[4] * kf2.x + q[5] * kf2.y + q[6] * kf3.x + q[7] * kf3.y;

        float mn = fmaxf(m, sc);
        float cOld = __expf(m - mn);
        float ex = __expf(sc - mn);
        den = den * cOld + ex;
        a[0] = a[0] * cOld + ex * vf0.x;
        a[1] = a[1] * cOld + ex * vf0.y;
        a[2] = a[2] * cOld + ex * vf1.x;
        a[3] = a[3] * cOld + ex * vf1.y;
        a[4] = a[4] * cOld + ex * vf2.x;
        a[5] = a[5] * cOld + ex * vf2.y;
        a[6] = a[6] * cOld + ex * vf3.x;
        a[7] = a[7] * cOld + ex * vf3.y;
        m = mn;
    }

    float inv = (den > 0.0f) ? 1.0f / den : 0.0f;
    float4* op = (float4*)(rc.acc + (size_t)node * 64 + h * 8);
    op[0] = make_float4(a[0] * inv, a[1] * inv, a[2] * inv, a[3] * inv);
    op[1] = make_float4(a[4] * inv, a[5] * inv, a[6] * inv, a[7] * inv);
}

// ---------------- final head ----------------
__global__ void out_kernel(const float* __restrict__ h, const float* __restrict__ Wo,
                           const float* __restrict__ bo, float* __restrict__ y, int n) {
    __shared__ float ws[256];
    __shared__ float bs[4];
    if (threadIdx.x < 256) ws[threadIdx.x] = Wo[threadIdx.x];
    if (threadIdx.x < 4) bs[threadIdx.x] = bo[threadIdx.x];
    __syncthreads();
    int node = blockIdx.x * blockDim.x + threadIdx.x;
    if (node >= n) return;
    const float4* hp = (const float4*)(h + (size_t)node * 64);
    float a0 = bs[0], a1 = bs[1], a2 = bs[2], a3 = bs[3];
    #pragma unroll
    for (int i = 0; i < 16; i++) {
        float4 hv = hp[i];
        const float* w = ws + 16 * i;
        a0 += hv.x * w[0]  + hv.y * w[4]  + hv.z * w[8]  + hv.w * w[12];
        a1 += hv.x * w[1]  + hv.y * w[5]  + hv.z * w[9]  + hv.w * w[13];
        a2 += hv.x * w[2]  + hv.y * w[6]  + hv.z * w[10] + hv.w * w[14];
        a3 += hv.x * w[3]  + hv.y * w[7]  + hv.z * w[11] + hv.w * w[15];
    }
    ((float4*)y)[node] = make_float4(a0, a1, a2, a3);
}

// ---------------- host launcher ----------------
static inline int cdiv(int a, int b) { return (a + b - 1) / b; }

extern "C" void kernel_launch(void* const* d_in, const int* in_sizes, int n_in,
                              void* d_out, int out_size) {
    (void)n_in; (void)out_size;

    const float* x[T_TYPES]   = {(const float*)d_in[0], (const float*)d_in[1],
                                 (const float*)d_in[2], (const float*)d_in[3]};
    const float* Win[T_TYPES] = {(const float*)d_in[4], (const float*)d_in[6],
                                 (const float*)d_in[8], (const float*)d_in[10]};
    const float* bin[T_TYPES] = {(const float*)d_in[5], (const float*)d_in[7],
                                 (const float*)d_in[9], (const float*)d_in[11]};

    const float *KW, *Kb, *QW, *Qb, *VW, *Vb, *AW, *Ab;
    if (in_sizes[13] > 4096) {
        KW = (const float*)d_in[12]; QW = (const float*)d_in[13];
        VW = (const float*)d_in[14]; AW = (const float*)d_in[15];
        Kb = (const float*)d_in[16]; Qb = (const float*)d_in[17];
        Vb = (const float*)d_in[18]; Ab = (const float*)d_in[19];
    } else {
        KW = (const float*)d_in[12]; Kb = (const float*)d_in[13];
        QW = (const float*)d_in[14]; Qb = (const float*)d_in[15];
        VW = (const float*)d_in[16]; Vb = (const float*)d_in[17];
        AW = (const float*)d_in[18]; Ab = (const float*)d_in[19];
    }
    const float* skip  = (const float*)d_in[20];
    const float* A_rel = (const float*)d_in[21];
    const float* M_rel = (const float*)d_in[22];
    const float* P_rel = (const float*)d_in[23];
    const float* W_out = (const float*)d_in[24];
    const float* b_out = (const float*)d_in[25];
    const int* ei[R_RELS] = {(const int*)d_in[26], (const int*)d_in[27], (const int*)d_in[28],
                             (const int*)d_in[29], (const int*)d_in[30], (const int*)d_in[31]};

    float *hB, *qB, *accB, *wktB, *wvtB, *bktB, *bvtB;
    __half* kvtB;
    unsigned* cntB;
    int *rowB, *curB, *bsumB, *srcsB;
    cudaGetSymbolAddress((void**)&hB,   g_h);
    cudaGetSymbolAddress((void**)&qB,   g_Q);
    cudaGetSymbolAddress((void**)&kvtB, g_KVt);
    cudaGetSymbolAddress((void**)&accB, g_acc);
    cudaGetSymbolAddress((void**)&wktB, g_Wkt);
    cudaGetSymbolAddress((void**)&wvtB, g_Wvt);
    cudaGetSymbolAddress((void**)&bktB, g_bkt);
    cudaGetSymbolAddress((void**)&bvtB, g_bvt);
    cudaGetSymbolAddress((void**)&cntB, g_cnt);
    cudaGetSymbolAddress((void**)&rowB, g_rowptr);
    cudaGetSymbolAddress((void**)&curB, g_cur);
    cudaGetSymbolAddress((void**)&bsumB, g_bsum);
    cudaGetSymbolAddress((void**)&srcsB, g_srcs);

    // ---- weight folding (once per launch) ----
    fold_kernel<<<LAYERS * R_RELS, 256>>>(KW, Kb, VW, Vb, A_rel, M_rel, P_rel,
                                          wktB, wvtB, bktB, bvtB);

    // ---- CSR build (once; edge lists constant across layers) ----
    fill4_u32<<<1024, 256>>>((uint4*)cntB, 0u, NDSUM / 4);
    for (int r = 0; r < R_RELS; r++) {
        count_kernel<<<cdiv(E_[r], 256), 256>>>(ei[r] + E_[r], cntB + CUMND_[r], E_[r]);
    }
    int nScanBlocks = cdiv(NDSUM, 2048);
    scan1_kernel<<<nScanBlocks, 256>>>(cntB, rowB, bsumB, NDSUM);
    scan2_kernel<<<1, 512>>>(bsumB, nScanBlocks);
    scan3_kernel<<<cdiv(NDSUM, 256), 256>>>(rowB, curB, bsumB, NDSUM, ESUM);
    for (int r = 0; r < R_RELS; r++) {
        scatter_kernel<<<cdiv(E_[r], 256), 256>>>(ei[r], ei[r] + E_[r],
                                                  curB + CUMND_[r], srcsB, E_[r]);
    }

    // ---- input projections (tensor cores) ----
    for (int t = 0; t < T_TYPES; t++) {
        tc_in_kernel<<<cdiv(N_[t], 128), 256>>>(
            x[t], Win[t], bin[t], hB + (size_t)OFF_[t] * HID, N_[t], F_[t]);
    }

    // relations for which each type is the source
    static const int relsBySrc[T_TYPES][3] = {{0, -1, -1}, {1, 2, 4}, {3, -1, -1}, {5, -1, -1}};
    static const int nRelsBySrc[T_TYPES]   = {1, 3, 1, 1};

    for (int l = 0; l < LAYERS; l++) {
        // Q + per-relation K~/V~ directly from h (tensor cores, folded weights)
        for (int t = 0; t < T_TYPES; t++) {
            int base = l * T_TYPES + t;
            KqvtCtx ctx;
            int np = 0;
            ctx.pass[np++] = {QW + (size_t)base * 4096, Qb + (size_t)base * 64,
                              qB + (size_t)OFF_[t] * HID, nullptr, 0};
            for (int i = 0; i < nRelsBySrc[t]; i++) {
                int r = relsBySrc[t][i];
                int lr = l * R_RELS + r;
                ctx.pass[np++] = {wktB + (size_t)lr * 4096, bktB + (size_t)lr * 64,
                                  nullptr, kvtB + (size_t)CUMSRC_[r] * 128, 0};
                ctx.pass[np++] = {wvtB + (size_t)lr * 4096, bvtB + (size_t)lr * 64,
                                  nullptr, kvtB + (size_t)CUMSRC_[r] * 128, 1};
            }
            ctx.nPass = np;
            tc_kqvt_kernel<<<cdiv(N_[t], 128), 256>>>(
                hB + (size_t)OFF_[t] * HID, ctx, N_[t]);
        }

        // attention over all relations, one launch
        AttnCtx p;
        for (int r = 0; r < R_RELS; r++) {
            int d = RD_[r];
            p.rel[r].KVt = kvtB + (size_t)CUMSRC_[r] * 128;
            p.rel[r].Q   = qB + (size_t)OFF_[d] * HID;
            p.rel[r].rowPtr = rowB + CUMND_[r];
            p.rel[r].acc = accB + (size_t)CUMND_[r] * HID;
            p.rel[r].Nd = N_[d];
        }
        for (int i = 0; i <= R_RELS; i++) p.blkOff[i] = ABLK_[i];
        attn_kernel<<<ATTN_BLOCKS, 256>>>(p, srcsB);

        // fused adapter per type (tensor cores); dst rels: author<-{1}, paper<-{0,3,5}, term<-{2}, conf<-{4}
        static const int relsByType[T_TYPES][3] = {{1, -1, -1}, {0, 3, 5}, {2, -1, -1}, {4, -1, -1}};
        for (int t = 0; t < T_TYPES; t++) {
            int base = l * T_TYPES + t;
            const float *a0 = accB + (size_t)CUMND_[relsByType[t][0]] * HID;
            const float *a1 = (relsByType[t][1] >= 0) ? accB + (size_t)CUMND_[relsByType[t][1]] * HID : nullptr;
            const float *a2 = (relsByType[t][2] >= 0) ? accB + (size_t)CUMND_[relsByType[t][2]] * HID : nullptr;
            tc_adapter_kernel<<<cdiv(N_[t], 128), 256>>>(
                a0, a1, a2,
                AW + (size_t)base * 4096, Ab + (size_t)base * 64,
                skip, base,
                hB + (size_t)OFF_[t] * HID, N_[t]);
        }
    }

    // final head on author nodes
    out_kernel<<<cdiv(N_[0], 256), 256>>>(hB, W_out, b_out, (float*)d_out, N_[0]);
}